// round 1
// baseline (speedup 1.0000x reference)
#include <cuda_runtime.h>
#include <math.h>

#define BB 16
#define CQ 256
#define CK 2048
#define NN 4096
#define NCLS 40

// ---- scratch (static __device__ arrays; no allocation) ----
__device__ float g_q[BB * NN * CQ];      // [b][n][c]   67 MB
__device__ float g_k[BB * CQ * NN];      // [b][c][n]   67 MB
__device__ float g_rowmax[BB * NN];
__device__ float g_rowsum[BB * NN];
__device__ float g_w[BB * NN];           // column-mean attention weights
__device__ float g_ximg[BB * CQ];
__device__ float g_imgmean[BB * CQ];
__device__ float g_xpc[BB * CK];
__device__ float g_fused[BB * (CQ + CK)];

// ============================================================
// Projection GEMM: out = W[M=256, KDIM] @ X[b][KDIM][NN] + bias
// OUT_T == 0 : store as [b][n][m]  (q layout)
// OUT_T == 1 : store as [b][m][n]  (k layout)
// block 256 thr, tile 64(m) x 64(n) x 32(k), 4x4 per thread
// ============================================================
template <int KDIM, int OUT_T>
__global__ void proj_kernel(const float* __restrict__ W,
                            const float* __restrict__ X,
                            const float* __restrict__ bias)
{
    const int b  = blockIdx.z;
    const int m0 = blockIdx.y * 64;
    const int n0 = blockIdx.x * 64;
    __shared__ float As[32][64];
    __shared__ float Bs[32][64];
    const int tid = threadIdx.x;
    const int tx = tid & 15, ty = tid >> 4;
    float acc[4][4] = {};
    const float* Xb = X + (size_t)b * KDIM * NN;

    for (int k0 = 0; k0 < KDIM; k0 += 32) {
        #pragma unroll
        for (int l = 0; l < 8; l++) {
            int idx = tid + l * 256;
            int mm = idx >> 5, kk = idx & 31;
            As[kk][mm] = W[(size_t)(m0 + mm) * KDIM + k0 + kk];
        }
        #pragma unroll
        for (int l = 0; l < 8; l++) {
            int idx = tid + l * 256;
            int kk = idx >> 6, nn = idx & 63;
            Bs[kk][nn] = Xb[(size_t)(k0 + kk) * NN + n0 + nn];
        }
        __syncthreads();
        #pragma unroll
        for (int kk = 0; kk < 32; kk++) {
            float a[4], bb[4];
            #pragma unroll
            for (int i = 0; i < 4; i++) a[i] = As[kk][ty * 4 + i];
            #pragma unroll
            for (int j = 0; j < 4; j++) bb[j] = Bs[kk][tx * 4 + j];
            #pragma unroll
            for (int i = 0; i < 4; i++)
                #pragma unroll
                for (int j = 0; j < 4; j++) acc[i][j] += a[i] * bb[j];
        }
        __syncthreads();
    }

    float* out = (OUT_T == 0) ? g_q : g_k;
    #pragma unroll
    for (int i = 0; i < 4; i++) {
        int m = m0 + ty * 4 + i;
        float bv = bias[m];
        #pragma unroll
        for (int j = 0; j < 4; j++) {
            int n = n0 + tx * 4 + j;
            float v = acc[i][j] + bv;
            if (OUT_T == 0)
                out[((size_t)b * NN + n) * CQ + m] = v;
            else
                out[((size_t)b * CQ + m) * NN + n] = v;
        }
    }
}

// ============================================================
// Pass 1: per-row (query) max & sum of exp of S = q @ k
// grid (NN/64 m-tiles, B) ; sweeps all n
// ============================================================
__global__ void attn_rowstats_kernel()
{
    const int b  = blockIdx.y;
    const int m0 = blockIdx.x * 64;
    __shared__ float As[32][64];
    __shared__ float Bs[32][64];
    const int tid = threadIdx.x;
    const int tx = tid & 15, ty = tid >> 4;
    const float* qb = g_q + (size_t)b * NN * CQ;
    const float* kb = g_k + (size_t)b * CQ * NN;

    float mx[4], sm[4];
    #pragma unroll
    for (int i = 0; i < 4; i++) { mx[i] = -INFINITY; sm[i] = 0.f; }

    for (int n0 = 0; n0 < NN; n0 += 64) {
        float acc[4][4] = {};
        for (int k0 = 0; k0 < CQ; k0 += 32) {
            #pragma unroll
            for (int l = 0; l < 8; l++) {
                int idx = tid + l * 256;
                int mm = idx >> 5, kk = idx & 31;
                As[kk][mm] = qb[(size_t)(m0 + mm) * CQ + k0 + kk];
            }
            #pragma unroll
            for (int l = 0; l < 8; l++) {
                int idx = tid + l * 256;
                int kk = idx >> 6, nn = idx & 63;
                Bs[kk][nn] = kb[(size_t)(k0 + kk) * NN + n0 + nn];
            }
            __syncthreads();
            #pragma unroll
            for (int kk = 0; kk < 32; kk++) {
                float a[4], bb[4];
                #pragma unroll
                for (int i = 0; i < 4; i++) a[i] = As[kk][ty * 4 + i];
                #pragma unroll
                for (int j = 0; j < 4; j++) bb[j] = Bs[kk][tx * 4 + j];
                #pragma unroll
                for (int i = 0; i < 4; i++)
                    #pragma unroll
                    for (int j = 0; j < 4; j++) acc[i][j] += a[i] * bb[j];
            }
            __syncthreads();
        }
        #pragma unroll
        for (int i = 0; i < 4; i++) {
            float t = fmaxf(fmaxf(acc[i][0], acc[i][1]), fmaxf(acc[i][2], acc[i][3]));
            float nm = fmaxf(mx[i], t);
            float s = sm[i] * __expf(mx[i] - nm);
            #pragma unroll
            for (int j = 0; j < 4; j++) s += __expf(acc[i][j] - nm);
            mx[i] = nm; sm[i] = s;
        }
    }
    // butterfly merge across the 16 tx lanes sharing each row group
    #pragma unroll
    for (int off = 8; off; off >>= 1) {
        #pragma unroll
        for (int i = 0; i < 4; i++) {
            float om = __shfl_xor_sync(0xffffffffu, mx[i], off);
            float os = __shfl_xor_sync(0xffffffffu, sm[i], off);
            float nm = fmaxf(mx[i], om);
            sm[i] = sm[i] * __expf(mx[i] - nm) + os * __expf(om - nm);
            mx[i] = nm;
        }
    }
    if (tx == 0) {
        #pragma unroll
        for (int i = 0; i < 4; i++) {
            int m = m0 + ty * 4 + i;
            g_rowmax[b * NN + m] = mx[i];
            g_rowsum[b * NN + m] = sm[i];
        }
    }
}

// ============================================================
// Pass 2: w[b][n] = (1/N) * sum_m exp(S[m,n]-rowmax[m]) / rowsum[m]
// grid (NN/64 n-tiles, B) ; sweeps all m ; exclusive write, no atomics
// ============================================================
__global__ void attn_wacc_kernel()
{
    const int b  = blockIdx.y;
    const int n0 = blockIdx.x * 64;
    __shared__ float As[32][64];
    __shared__ float Bs[32][64];
    __shared__ float red[16][64];
    const int tid = threadIdx.x;
    const int tx = tid & 15, ty = tid >> 4;
    const float* qb = g_q + (size_t)b * NN * CQ;
    const float* kb = g_k + (size_t)b * CQ * NN;

    float colacc[4] = {};
    for (int m0 = 0; m0 < NN; m0 += 64) {
        float acc[4][4] = {};
        for (int k0 = 0; k0 < CQ; k0 += 32) {
            #pragma unroll
            for (int l = 0; l < 8; l++) {
                int idx = tid + l * 256;
                int mm = idx >> 5, kk = idx & 31;
                As[kk][mm] = qb[(size_t)(m0 + mm) * CQ + k0 + kk];
            }
            #pragma unroll
            for (int l = 0; l < 8; l++) {
                int idx = tid + l * 256;
                int kk = idx >> 6, nn = idx & 63;
                Bs[kk][nn] = kb[(size_t)(k0 + kk) * NN + n0 + nn];
            }
            __syncthreads();
            #pragma unroll
            for (int kk = 0; kk < 32; kk++) {
                float a[4], bb[4];
                #pragma unroll
                for (int i = 0; i < 4; i++) a[i] = As[kk][ty * 4 + i];
                #pragma unroll
                for (int j = 0; j < 4; j++) bb[j] = Bs[kk][tx * 4 + j];
                #pragma unroll
                for (int i = 0; i < 4; i++)
                    #pragma unroll
                    for (int j = 0; j < 4; j++) acc[i][j] += a[i] * bb[j];
            }
            __syncthreads();
        }
        float rm[4], ri[4];
        #pragma unroll
        for (int i = 0; i < 4; i++) {
            int m = m0 + ty * 4 + i;
            rm[i] = g_rowmax[b * NN + m];
            ri[i] = 1.0f / g_rowsum[b * NN + m];
        }
        #pragma unroll
        for (int i = 0; i < 4; i++)
            #pragma unroll
            for (int j = 0; j < 4; j++)
                colacc[j] += __expf(acc[i][j] - rm[i]) * ri[i];
    }
    #pragma unroll
    for (int j = 0; j < 4; j++) red[ty][tx * 4 + j] = colacc[j];
    __syncthreads();
    if (tid < 64) {
        float s = 0.f;
        #pragma unroll
        for (int t = 0; t < 16; t++) s += red[t][tid];
        g_w[b * NN + n0 + tid] = s * (1.0f / NN);
    }
}

// ============================================================
// Weighted/plain reductions over spatial axis
// grid (2304, B), block 128 ; c<256 -> img (x_img + mean), else pc2d (x_pc)
// ============================================================
__global__ void reduce_xw_kernel(const float* __restrict__ img,
                                 const float* __restrict__ pc2d)
{
    const int b = blockIdx.y;
    const int c = blockIdx.x;
    const int t = threadIdx.x;
    const float* wv = g_w + b * NN;
    __shared__ float s1s[4], s2s[4];

    float s1 = 0.f, s2 = 0.f;
    if (c < CQ) {
        const float* row = img + ((size_t)b * CQ + c) * NN;
        for (int n = t; n < NN; n += 128) { float x = row[n]; s1 += x * wv[n]; s2 += x; }
    } else {
        const float* row = pc2d + ((size_t)b * CK + (c - CQ)) * NN;
        for (int n = t; n < NN; n += 128) s1 += row[n] * wv[n];
    }
    #pragma unroll
    for (int o = 16; o; o >>= 1) {
        s1 += __shfl_xor_sync(0xffffffffu, s1, o);
        s2 += __shfl_xor_sync(0xffffffffu, s2, o);
    }
    if ((t & 31) == 0) { s1s[t >> 5] = s1; s2s[t >> 5] = s2; }
    __syncthreads();
    if (t == 0) {
        float a = s1s[0] + s1s[1] + s1s[2] + s1s[3];
        float m = s2s[0] + s2s[1] + s2s[2] + s2s[3];
        if (c < CQ) {
            g_ximg[b * CQ + c] = a;
            g_imgmean[b * CQ + c] = m * (1.0f / NN);
        } else {
            g_xpc[b * CK + (c - CQ)] = a;
        }
    }
}

// ============================================================
// Fused vector: [0,256)  = gamma*(Wvi@x_img + bvi) + imgmean
//               [256,..) = Wvp@x_pc + bvp
// grid (9, B), block 256
// ============================================================
__global__ void fuse_kernel(const float* __restrict__ Wvi, const float* __restrict__ bvi,
                            const float* __restrict__ Wvp, const float* __restrict__ bvp,
                            const float* __restrict__ gamma1)
{
    const int b = blockIdx.y;
    const int chunk = blockIdx.x;
    const int t = threadIdx.x;
    __shared__ float xs[2048];

    if (chunk == 0) {
        if (t < CQ) xs[t] = g_ximg[b * CQ + t];
        __syncthreads();
        float acc = 0.f;
        const float* wr = Wvi + (size_t)t * CQ;
        for (int i = 0; i < CQ; i++) acc += wr[i] * xs[i];
        float g = gamma1[0];
        g_fused[b * (CQ + CK) + t] = g * (acc + bvi[t]) + g_imgmean[b * CQ + t];
    } else {
        for (int i = t; i < CK; i += 256) xs[i] = g_xpc[b * CK + i];
        __syncthreads();
        int c2 = (chunk - 1) * 256 + t;
        float acc = 0.f;
        const float* wr = Wvp + (size_t)c2 * CK;
        for (int i = 0; i < CK; i++) acc += wr[i] * xs[i];
        g_fused[b * (CQ + CK) + CQ + c2] = acc + bvp[c2];
    }
}

// ============================================================
// MLP head + log_softmax ; grid (B), block 256
// ============================================================
__device__ __forceinline__ float warp_red(float v)
{
    #pragma unroll
    for (int o = 16; o; o >>= 1) v += __shfl_xor_sync(0xffffffffu, v, o);
    return v;
}

__global__ void head_kernel(const float* __restrict__ W1, const float* __restrict__ b1,
                            const float* __restrict__ W2, const float* __restrict__ b2,
                            float* __restrict__ out)
{
    const int b = blockIdx.x;
    __shared__ float fs[CQ + CK];
    __shared__ float hs[1024];
    __shared__ float lg[NCLS];
    __shared__ float mxs, lses;
    const int tid = threadIdx.x;
    const int warp = tid >> 5, lane = tid & 31;

    for (int i = tid; i < CQ + CK; i += 256) fs[i] = g_fused[b * (CQ + CK) + i];
    __syncthreads();

    for (int j = warp; j < 1024; j += 8) {
        const float* wr = W1 + (size_t)j * (CQ + CK);
        float s = 0.f;
        for (int i = lane; i < CQ + CK; i += 32) s += fs[i] * wr[i];
        s = warp_red(s);
        if (lane == 0) hs[j] = fmaxf(s + b1[j], 0.f);
    }
    __syncthreads();

    for (int k = warp; k < NCLS; k += 8) {
        const float* wr = W2 + (size_t)k * 1024;
        float s = 0.f;
        for (int i = lane; i < 1024; i += 32) s += hs[i] * wr[i];
        s = warp_red(s);
        if (lane == 0) lg[k] = s + b2[k];
    }
    __syncthreads();

    if (tid == 0) {
        float m = -INFINITY;
        for (int k = 0; k < NCLS; k++) m = fmaxf(m, lg[k]);
        float s = 0.f;
        for (int k = 0; k < NCLS; k++) s += expf(lg[k] - m);
        mxs = m; lses = logf(s);
    }
    __syncthreads();
    if (tid < NCLS) out[b * NCLS + tid] = lg[tid] - mxs - lses;
}

// ============================================================
extern "C" void kernel_launch(void* const* d_in, const int* in_sizes, int n_in,
                              void* d_out, int out_size)
{
    const float* img    = (const float*)d_in[0];
    const float* pc2d   = (const float*)d_in[1];
    const float* Wq     = (const float*)d_in[2];
    const float* bq     = (const float*)d_in[3];
    const float* Wk     = (const float*)d_in[4];
    const float* bk     = (const float*)d_in[5];
    const float* Wvi    = (const float*)d_in[6];
    const float* bvi    = (const float*)d_in[7];
    const float* Wvp    = (const float*)d_in[8];
    const float* bvp    = (const float*)d_in[9];
    const float* gamma1 = (const float*)d_in[10];
    const float* W1     = (const float*)d_in[11];
    const float* b1     = (const float*)d_in[12];
    const float* W2     = (const float*)d_in[13];
    const float* b2     = (const float*)d_in[14];
    float* out = (float*)d_out;

    dim3 blk(256);
    // q = Wq @ img + bq     -> g_q [b][n][c]
    proj_kernel<CQ, 0><<<dim3(NN / 64, CQ / 64, BB), blk>>>(Wq, img, bq);
    // k = Wk @ pc2d + bk    -> g_k [b][c][n]
    proj_kernel<CK, 1><<<dim3(NN / 64, CQ / 64, BB), blk>>>(Wk, pc2d, bk);
    // softmax row stats
    attn_rowstats_kernel<<<dim3(NN / 64, BB), blk>>>();
    // column-mean weights w
    attn_wacc_kernel<<<dim3(NN / 64, BB), blk>>>();
    // weighted reductions over spatial
    reduce_xw_kernel<<<dim3(CQ + CK, BB), dim3(128)>>>(img, pc2d);
    // fused feature vector
    fuse_kernel<<<dim3(1 + CK / 256, BB), blk>>>(Wvi, bvi, Wvp, bvp, gamma1);
    // MLP head + log_softmax
    head_kernel<<<dim3(BB), blk>>>(W1, b1, W2, b2, out);
}

// round 3
// speedup vs baseline: 5.5765x; 5.5765x over previous
#include <cuda_runtime.h>
#include <math.h>
#include <stdint.h>

#define BB 16
#define CQ 256
#define CK 2048
#define NN 4096
#define NCLS 40

// ---- scratch (static __device__ arrays; no allocation) ----
__device__ float g_q[(size_t)BB * CQ * NN];          // [b][c][n] tf32-rounded fp32, 67MB
__device__ float g_k[(size_t)BB * CQ * NN];          // [b][c][n] tf32-rounded fp32, 67MB
__device__ float g_S[(size_t)BB * NN * NN];          // [b][m][n] fp32, 1.07GB
__device__ float g_rowmax[BB * NN];
__device__ float g_rowsum[BB * NN];
__device__ float g_wpart[16 * BB * NN];              // per-m-slice partial column sums
__device__ float g_w[BB * NN];
__device__ float g_ximg[BB * CQ];
__device__ float g_imgmean[BB * CQ];
__device__ float g_xpc[BB * CK];
__device__ float g_fused[BB * (CQ + CK)];

// ============================================================
// helpers
// ============================================================
__device__ __forceinline__ uint32_t smem_u32(const void* p) {
    uint32_t a;
    asm("{ .reg .u64 t; cvta.to.shared.u64 t, %1; cvt.u32.u64 %0, t; }" : "=r"(a) : "l"(p));
    return a;
}
__device__ __forceinline__ uint32_t f2tf32(float f) {
    uint32_t u;
    asm("cvt.rna.tf32.f32 %0, %1;" : "=r"(u) : "f"(f));
    return u;
}
__device__ __forceinline__ void mma_tf32(float* c, uint32_t a0, uint32_t a1, uint32_t a2, uint32_t a3,
                                         uint32_t b0, uint32_t b1)
{
    asm volatile(
        "mma.sync.aligned.m16n8k8.row.col.f32.tf32.tf32.f32 "
        "{%0,%1,%2,%3},{%4,%5,%6,%7},{%8,%9},{%0,%1,%2,%3};"
        : "+f"(c[0]), "+f"(c[1]), "+f"(c[2]), "+f"(c[3])
        : "r"(a0), "r"(a1), "r"(a2), "r"(a3), "r"(b0), "r"(b1));
}
#define CP_A16(dst, src) \
    asm volatile("cp.async.ca.shared.global [%0], [%1], 16;" :: "r"(dst), "l"(src))
#define CP_COMMIT() asm volatile("cp.async.commit_group;" ::: "memory")
#define CP_WAIT0()  asm volatile("cp.async.wait_group 0;" ::: "memory")

// ============================================================
// Projection GEMM (tf32 mma): out[b][m][n] = W[m,:]·X[b][:,n] + bias[m]
// (tf32-rounded output). Block: 128m x 128n, K-chunks of 64, cp.async
// double-buffered. Warp = 16-row m-strip x full 128 n (16 mma tiles).
// ============================================================
#define PROJ_SMEM ((2 * 8704 + 2 * 8704) * 4)

template <int KDIM, int WHICH>
__global__ __launch_bounds__(256) void proj_kernel(const float* __restrict__ W,
                                                   const float* __restrict__ X,
                                                   const float* __restrict__ bias)
{
    extern __shared__ float sm[];
    float* As[2] = { sm, sm + 8704 };                 // [128 m][68 k-pad]
    float* Bs[2] = { sm + 17408, sm + 17408 + 8704 }; // [64 k][136 n-pad]

    const int b  = blockIdx.z;
    const int m0 = blockIdx.y * 128;
    const int n0 = blockIdx.x * 128;
    const int tid = threadIdx.x;
    const int lane = tid & 31, w = tid >> 5;
    const int gid = lane >> 2, tig = lane & 3;
    const int wm = w * 16;
    const int NCH = KDIM / 64;

    float acc[16][4];
    #pragma unroll
    for (int t = 0; t < 16; t++)
        #pragma unroll
        for (int j = 0; j < 4; j++) acc[t][j] = 0.f;

    // issue chunk 0
    {
        #pragma unroll
        for (int l = 0; l < 8; l++) {
            int i = tid + l * 256;
            int r = i >> 4, c4 = i & 15;
            CP_A16(smem_u32(As[0] + r * 68 + c4 * 4), W + (size_t)(m0 + r) * KDIM + c4 * 4);
        }
        #pragma unroll
        for (int l = 0; l < 8; l++) {
            int i = tid + l * 256;
            int r = i >> 5, c4 = i & 31;
            CP_A16(smem_u32(Bs[0] + r * 136 + c4 * 4), X + ((size_t)b * KDIM + r) * NN + n0 + c4 * 4);
        }
        CP_COMMIT();
        CP_WAIT0();
        __syncthreads();
    }

    for (int kc = 0; kc < NCH; kc++) {
        const int cur = kc & 1, nxt = cur ^ 1;
        if (kc + 1 < NCH) {
            const int kb = (kc + 1) * 64;
            #pragma unroll
            for (int l = 0; l < 8; l++) {
                int i = tid + l * 256;
                int r = i >> 4, c4 = i & 15;
                CP_A16(smem_u32(As[nxt] + r * 68 + c4 * 4),
                       W + (size_t)(m0 + r) * KDIM + kb + c4 * 4);
            }
            #pragma unroll
            for (int l = 0; l < 8; l++) {
                int i = tid + l * 256;
                int r = i >> 5, c4 = i & 31;
                CP_A16(smem_u32(Bs[nxt] + r * 136 + c4 * 4),
                       X + ((size_t)b * KDIM + kb + r) * NN + n0 + c4 * 4);
            }
        }
        CP_COMMIT();

        const float* Ac = As[cur];
        const float* Bc = Bs[cur];
        #pragma unroll
        for (int ks = 0; ks < 8; ks++) {
            const float* ab = Ac + (wm + gid) * 68 + ks * 8 + tig;
            uint32_t a0 = f2tf32(ab[0]);
            uint32_t a1 = f2tf32(ab[8 * 68]);
            uint32_t a2 = f2tf32(ab[4]);
            uint32_t a3 = f2tf32(ab[8 * 68 + 4]);
            const float* bb = Bc + (ks * 8 + tig) * 136 + gid;
            #pragma unroll
            for (int t = 0; t < 16; t++) {
                uint32_t b0 = f2tf32(bb[t * 8]);
                uint32_t b1 = f2tf32(bb[4 * 136 + t * 8]);
                mma_tf32(acc[t], a0, a1, a2, a3, b0, b1);
            }
        }
        CP_WAIT0();
        __syncthreads();
    }

    // epilogue: + bias, tf32-round, store out[b][m][n]
    float* out = (WHICH == 0) ? g_q : g_k;
    const int R0 = m0 + wm + gid;
    const float bv0 = bias[R0], bv1 = bias[R0 + 8];
    float* o0 = out + ((size_t)b * CQ + R0) * NN + n0;
    float* o1 = o0 + (size_t)8 * NN;
    #pragma unroll
    for (int t = 0; t < 16; t++) {
        int col = t * 8 + tig * 2;
        float2 v0, v1;
        v0.x = __uint_as_float(f2tf32(acc[t][0] + bv0));
        v0.y = __uint_as_float(f2tf32(acc[t][1] + bv0));
        v1.x = __uint_as_float(f2tf32(acc[t][2] + bv1));
        v1.y = __uint_as_float(f2tf32(acc[t][3] + bv1));
        *reinterpret_cast<float2*>(o0 + col) = v0;
        *reinterpret_cast<float2*>(o1 + col) = v1;
    }
}

// ============================================================
// Attention pass 1 (tf32 mma): per (b, 128-row m-tile), sweep all n.
// S tile -> g_S; per-row online (max, sumexp) from accumulators.
// A (q-tile, all 256 k) resident in smem; B (k-tensor) double-buffered.
// ============================================================
#define P1_SMEM ((34816 + 2 * 8704) * 4)

__global__ __launch_bounds__(256) void attn_pass1()
{
    extern __shared__ float sm[];
    float* As    = sm;                    // [256 k][136 m-pad]
    float* Bs[2] = { sm + 34816, sm + 34816 + 8704 };  // [64 k][136 n-pad]

    const int b  = blockIdx.y;
    const int m0 = blockIdx.x * 128;
    const int tid = threadIdx.x;
    const int lane = tid & 31, w = tid >> 5;
    const int gid = lane >> 2, tig = lane & 3;
    const int wm = w * 16;

    // load full q-tile (256 ch x 128 spatial) -> As[k][m], + first B chunk
    #pragma unroll
    for (int l = 0; l < 34; l++) {
        int i = tid + l * 256;
        int r = i >> 5, c4 = i & 31;
        CP_A16(smem_u32(As + r * 136 + c4 * 4), g_q + ((size_t)b * CQ + r) * NN + m0 + c4 * 4);
    }
    #pragma unroll
    for (int l = 0; l < 8; l++) {
        int i = tid + l * 256;
        int r = i >> 5, c4 = i & 31;
        CP_A16(smem_u32(Bs[0] + r * 136 + c4 * 4), g_k + ((size_t)b * CQ + r) * NN + c4 * 4);
    }
    CP_COMMIT();
    CP_WAIT0();
    __syncthreads();

    float acc[16][4];
    #pragma unroll
    for (int t = 0; t < 16; t++)
        #pragma unroll
        for (int j = 0; j < 4; j++) acc[t][j] = 0.f;

    float run_m0 = -INFINITY, run_m1 = -INFINITY, run_s0 = 0.f, run_s1 = 0.f;
    const int R0 = m0 + wm + gid;

    for (int g = 0; g < 128; g++) {          // 32 n-chunks x 4 k-chunks
        const int cur = g & 1, nxt = cur ^ 1;
        if (g + 1 < 128) {
            const int nkc = (g + 1) & 3, nnc = (g + 1) >> 2;
            #pragma unroll
            for (int l = 0; l < 8; l++) {
                int i = tid + l * 256;
                int r = i >> 5, c4 = i & 31;
                CP_A16(smem_u32(Bs[nxt] + r * 136 + c4 * 4),
                       g_k + ((size_t)b * CQ + nkc * 64 + r) * NN + nnc * 128 + c4 * 4);
            }
        }
        CP_COMMIT();

        const int kc = g & 3;
        const float* Bc = Bs[cur];
        #pragma unroll
        for (int ks = 0; ks < 8; ks++) {
            const float* ab = As + (kc * 64 + ks * 8 + tig) * 136 + wm + gid;
            uint32_t a0 = __float_as_uint(ab[0]);
            uint32_t a1 = __float_as_uint(ab[8]);
            uint32_t a2 = __float_as_uint(ab[4 * 136]);
            uint32_t a3 = __float_as_uint(ab[4 * 136 + 8]);
            const float* bb = Bc + (ks * 8 + tig) * 136 + gid;
            #pragma unroll
            for (int t = 0; t < 16; t++) {
                uint32_t b0 = __float_as_uint(bb[t * 8]);
                uint32_t b1 = __float_as_uint(bb[4 * 136 + t * 8]);
                mma_tf32(acc[t], a0, a1, a2, a3, b0, b1);
            }
        }

        if (kc == 3) {                       // n-chunk complete: epilogue
            const int nc = g >> 2;
            // local max per row
            float vm0 = -INFINITY, vm1 = -INFINITY;
            #pragma unroll
            for (int t = 0; t < 16; t++) {
                vm0 = fmaxf(vm0, fmaxf(acc[t][0], acc[t][1]));
                vm1 = fmaxf(vm1, fmaxf(acc[t][2], acc[t][3]));
            }
            vm0 = fmaxf(vm0, __shfl_xor_sync(0xffffffffu, vm0, 1));
            vm0 = fmaxf(vm0, __shfl_xor_sync(0xffffffffu, vm0, 2));
            vm1 = fmaxf(vm1, __shfl_xor_sync(0xffffffffu, vm1, 1));
            vm1 = fmaxf(vm1, __shfl_xor_sync(0xffffffffu, vm1, 2));
            float nm0 = fmaxf(run_m0, vm0);
            float nm1 = fmaxf(run_m1, vm1);
            float s0 = 0.f, s1 = 0.f;
            #pragma unroll
            for (int t = 0; t < 16; t++) {
                s0 += __expf(acc[t][0] - nm0) + __expf(acc[t][1] - nm0);
                s1 += __expf(acc[t][2] - nm1) + __expf(acc[t][3] - nm1);
            }
            s0 += __shfl_xor_sync(0xffffffffu, s0, 1);
            s0 += __shfl_xor_sync(0xffffffffu, s0, 2);
            s1 += __shfl_xor_sync(0xffffffffu, s1, 1);
            s1 += __shfl_xor_sync(0xffffffffu, s1, 2);
            run_s0 = run_s0 * __expf(run_m0 - nm0) + s0;
            run_s1 = run_s1 * __expf(run_m1 - nm1) + s1;
            run_m0 = nm0;
            run_m1 = nm1;
            // store S tile
            float* so0 = g_S + ((size_t)b * NN + R0) * NN + nc * 128;
            float* so1 = so0 + (size_t)8 * NN;
            #pragma unroll
            for (int t = 0; t < 16; t++) {
                int col = t * 8 + tig * 2;
                *reinterpret_cast<float2*>(so0 + col) = make_float2(acc[t][0], acc[t][1]);
                *reinterpret_cast<float2*>(so1 + col) = make_float2(acc[t][2], acc[t][3]);
            }
            #pragma unroll
            for (int t = 0; t < 16; t++)
                #pragma unroll
                for (int j = 0; j < 4; j++) acc[t][j] = 0.f;
        }
        CP_WAIT0();
        __syncthreads();
    }

    if (tig == 0) {
        g_rowmax[b * NN + R0]     = run_m0;
        g_rowsum[b * NN + R0]     = run_s0;
        g_rowmax[b * NN + R0 + 8] = run_m1;
        g_rowsum[b * NN + R0 + 8] = run_s1;
    }
}

// ============================================================
// Attention pass 2: stream S, accumulate per-slice column sums.
// grid (4 n-chunks, 16 m-slices, B), block 256; thread owns 4 columns.
// ============================================================
__global__ __launch_bounds__(256) void attn_pass2()
{
    __shared__ float rm[256], rz[256];
    const int b  = blockIdx.z;
    const int ms = blockIdx.y;
    const int nb = blockIdx.x * 1024;
    const int tid = threadIdx.x;

    rm[tid] = g_rowmax[b * NN + ms * 256 + tid];
    rz[tid] = 1.0f / g_rowsum[b * NN + ms * 256 + tid];
    __syncthreads();

    const float* Sp = g_S + ((size_t)b * NN + ms * 256) * NN + nb + tid * 4;
    float4 acc = make_float4(0.f, 0.f, 0.f, 0.f);
    for (int m = 0; m < 256; m++) {
        float4 s = *reinterpret_cast<const float4*>(Sp + (size_t)m * NN);
        float mx = rm[m], z = rz[m];
        acc.x += __expf(s.x - mx) * z;
        acc.y += __expf(s.y - mx) * z;
        acc.z += __expf(s.z - mx) * z;
        acc.w += __expf(s.w - mx) * z;
    }
    const float sc = 1.0f / NN;
    acc.x *= sc; acc.y *= sc; acc.z *= sc; acc.w *= sc;
    *reinterpret_cast<float4*>(g_wpart + (size_t)ms * (BB * NN) + b * NN + nb + tid * 4) = acc;
}

__global__ void reduce_w_kernel()
{
    const int flat = blockIdx.x * 256 + threadIdx.x;
    float s = 0.f;
    #pragma unroll
    for (int ms = 0; ms < 16; ms++) s += g_wpart[ms * (BB * NN) + flat];
    g_w[flat] = s;
}

// ============================================================
// Weighted/plain reductions over spatial axis
// ============================================================
__global__ void reduce_xw_kernel(const float* __restrict__ img,
                                 const float* __restrict__ pc2d)
{
    const int b = blockIdx.y;
    const int c = blockIdx.x;
    const int t = threadIdx.x;
    const float* wv = g_w + b * NN;
    __shared__ float s1s[4], s2s[4];

    float s1 = 0.f, s2 = 0.f;
    if (c < CQ) {
        const float* row = img + ((size_t)b * CQ + c) * NN;
        for (int n = t; n < NN; n += 128) { float x = row[n]; s1 += x * wv[n]; s2 += x; }
    } else {
        const float* row = pc2d + ((size_t)b * CK + (c - CQ)) * NN;
        for (int n = t; n < NN; n += 128) s1 += row[n] * wv[n];
    }
    #pragma unroll
    for (int o = 16; o; o >>= 1) {
        s1 += __shfl_xor_sync(0xffffffffu, s1, o);
        s2 += __shfl_xor_sync(0xffffffffu, s2, o);
    }
    if ((t & 31) == 0) { s1s[t >> 5] = s1; s2s[t >> 5] = s2; }
    __syncthreads();
    if (t == 0) {
        float a = s1s[0] + s1s[1] + s1s[2] + s1s[3];
        float m = s2s[0] + s2s[1] + s2s[2] + s2s[3];
        if (c < CQ) {
            g_ximg[b * CQ + c] = a;
            g_imgmean[b * CQ + c] = m * (1.0f / NN);
        } else {
            g_xpc[b * CK + (c - CQ)] = a;
        }
    }
}

// ============================================================
// Fused vector
// ============================================================
__global__ void fuse_kernel(const float* __restrict__ Wvi, const float* __restrict__ bvi,
                            const float* __restrict__ Wvp, const float* __restrict__ bvp,
                            const float* __restrict__ gamma1)
{
    const int b = blockIdx.y;
    const int chunk = blockIdx.x;
    const int t = threadIdx.x;
    __shared__ float xs[2048];

    if (chunk == 0) {
        if (t < CQ) xs[t] = g_ximg[b * CQ + t];
        __syncthreads();
        float acc = 0.f;
        const float* wr = Wvi + (size_t)t * CQ;
        for (int i = 0; i < CQ; i++) acc += wr[i] * xs[i];
        float g = gamma1[0];
        g_fused[b * (CQ + CK) + t] = g * (acc + bvi[t]) + g_imgmean[b * CQ + t];
    } else {
        for (int i = t; i < CK; i += 256) xs[i] = g_xpc[b * CK + i];
        __syncthreads();
        int c2 = (chunk - 1) * 256 + t;
        float acc = 0.f;
        const float* wr = Wvp + (size_t)c2 * CK;
        for (int i = 0; i < CK; i++) acc += wr[i] * xs[i];
        g_fused[b * (CQ + CK) + CQ + c2] = acc + bvp[c2];
    }
}

// ============================================================
// MLP head + log_softmax
// ============================================================
__device__ __forceinline__ float warp_red(float v)
{
    #pragma unroll
    for (int o = 16; o; o >>= 1) v += __shfl_xor_sync(0xffffffffu, v, o);
    return v;
}

__global__ void head_kernel(const float* __restrict__ W1, const float* __restrict__ b1,
                            const float* __restrict__ W2, const float* __restrict__ b2,
                            float* __restrict__ out)
{
    const int b = blockIdx.x;
    __shared__ float fs[CQ + CK];
    __shared__ float hs[1024];
    __shared__ float lg[NCLS];
    __shared__ float mxs, lses;
    const int tid = threadIdx.x;
    const int warp = tid >> 5, lane = tid & 31;

    for (int i = tid; i < CQ + CK; i += 256) fs[i] = g_fused[b * (CQ + CK) + i];
    __syncthreads();

    for (int j = warp; j < 1024; j += 8) {
        const float* wr = W1 + (size_t)j * (CQ + CK);
        float s = 0.f;
        for (int i = lane; i < CQ + CK; i += 32) s += fs[i] * wr[i];
        s = warp_red(s);
        if (lane == 0) hs[j] = fmaxf(s + b1[j], 0.f);
    }
    __syncthreads();

    for (int k = warp; k < NCLS; k += 8) {
        const float* wr = W2 + (size_t)k * 1024;
        float s = 0.f;
        for (int i = lane; i < 1024; i += 32) s += hs[i] * wr[i];
        s = warp_red(s);
        if (lane == 0) lg[k] = s + b2[k];
    }
    __syncthreads();

    if (tid == 0) {
        float m = -INFINITY;
        for (int k = 0; k < NCLS; k++) m = fmaxf(m, lg[k]);
        float s = 0.f;
        for (int k = 0; k < NCLS; k++) s += expf(lg[k] - m);
        mxs = m; lses = logf(s);
    }
    __syncthreads();
    if (tid < NCLS) out[b * NCLS + tid] = lg[tid] - mxs - lses;
}

// ============================================================
extern "C" void kernel_launch(void* const* d_in, const int* in_sizes, int n_in,
                              void* d_out, int out_size)
{
    const float* img    = (const float*)d_in[0];
    const float* pc2d   = (const float*)d_in[1];
    const float* Wq     = (const float*)d_in[2];
    const float* bq     = (const float*)d_in[3];
    const float* Wk     = (const float*)d_in[4];
    const float* bk     = (const float*)d_in[5];
    const float* Wvi    = (const float*)d_in[6];
    const float* bvi    = (const float*)d_in[7];
    const float* Wvp    = (const float*)d_in[8];
    const float* bvp    = (const float*)d_in[9];
    const float* gamma1 = (const float*)d_in[10];
    const float* W1     = (const float*)d_in[11];
    const float* b1     = (const float*)d_in[12];
    const float* W2     = (const float*)d_in[13];
    const float* b2     = (const float*)d_in[14];
    float* out = (float*)d_out;

    cudaFuncSetAttribute(proj_kernel<CQ, 0>, cudaFuncAttributeMaxDynamicSharedMemorySize, PROJ_SMEM);
    cudaFuncSetAttribute(proj_kernel<CK, 1>, cudaFuncAttributeMaxDynamicSharedMemorySize, PROJ_SMEM);
    cudaFuncSetAttribute(attn_pass1, cudaFuncAttributeMaxDynamicSharedMemorySize, P1_SMEM);

    dim3 blk(256);
    proj_kernel<CQ, 0><<<dim3(NN / 128, CQ / 128, BB), blk, PROJ_SMEM>>>(Wq, img, bq);
    proj_kernel<CK, 1><<<dim3(NN / 128, CQ / 128, BB), blk, PROJ_SMEM>>>(Wk, pc2d, bk);
    attn_pass1<<<dim3(NN / 128, BB), blk, P1_SMEM>>>();
    attn_pass2<<<dim3(4, 16, BB), blk>>>();
    reduce_w_kernel<<<dim3(BB * NN / 256), blk>>>();
    reduce_xw_kernel<<<dim3(CQ + CK, BB), dim3(128)>>>(img, pc2d);
    fuse_kernel<<<dim3(1 + CK / 256, BB), blk>>>(Wvi, bvi, Wvp, bvp, gamma1);
    head_kernel<<<dim3(BB), blk>>>(W1, b1, W2, b2, out);
}

// round 4
// speedup vs baseline: 7.1893x; 1.2892x over previous
#include <cuda_runtime.h>
#include <cuda_bf16.h>
#include <math.h>
#include <stdint.h>

#define BB 16
#define CQ 256
#define CK 2048
#define NN 4096
#define NCLS 40

// ---- scratch (static __device__ arrays; no allocation) ----
__device__ __nv_bfloat16 g_qh[(size_t)BB * NN * CQ];  // [b][n][c] bf16, 32MB
__device__ __nv_bfloat16 g_kh[(size_t)BB * NN * CQ];  // [b][n][c] bf16, 32MB
__device__ float g_S[(size_t)BB * NN * NN];           // [b][m][n] fp32, 1.07GB
__device__ float g_rowmax[BB * NN];
__device__ float g_rowsum[BB * NN];
__device__ float g_wpart[16 * BB * NN];
__device__ float g_w[BB * NN];
__device__ float g_ximg[BB * CQ];
__device__ float g_imgmean[BB * CQ];
__device__ float g_xpc[BB * CK];
__device__ float g_fused[BB * (CQ + CK)];

// ============================================================
// helpers
// ============================================================
__device__ __forceinline__ uint32_t smem_u32(const void* p) {
    uint32_t a;
    asm("{ .reg .u64 t; cvta.to.shared.u64 t, %1; cvt.u32.u64 %0, t; }" : "=r"(a) : "l"(p));
    return a;
}
__device__ __forceinline__ uint32_t f2tf32(float f) {
    uint32_t u;
    asm("cvt.rna.tf32.f32 %0, %1;" : "=r"(u) : "f"(f));
    return u;
}
__device__ __forceinline__ void mma_tf32(float* c, uint32_t a0, uint32_t a1, uint32_t a2, uint32_t a3,
                                         uint32_t b0, uint32_t b1)
{
    asm volatile(
        "mma.sync.aligned.m16n8k8.row.col.f32.tf32.tf32.f32 "
        "{%0,%1,%2,%3},{%4,%5,%6,%7},{%8,%9},{%0,%1,%2,%3};"
        : "+f"(c[0]), "+f"(c[1]), "+f"(c[2]), "+f"(c[3])
        : "r"(a0), "r"(a1), "r"(a2), "r"(a3), "r"(b0), "r"(b1));
}
__device__ __forceinline__ void mma_bf16(float* c, uint32_t a0, uint32_t a1, uint32_t a2, uint32_t a3,
                                         uint32_t b0, uint32_t b1)
{
    asm volatile(
        "mma.sync.aligned.m16n8k16.row.col.f32.bf16.bf16.f32 "
        "{%0,%1,%2,%3},{%4,%5,%6,%7},{%8,%9},{%0,%1,%2,%3};"
        : "+f"(c[0]), "+f"(c[1]), "+f"(c[2]), "+f"(c[3])
        : "r"(a0), "r"(a1), "r"(a2), "r"(a3), "r"(b0), "r"(b1));
}
#define CP_A16(dst, src) \
    asm volatile("cp.async.ca.shared.global [%0], [%1], 16;" :: "r"(dst), "l"(src))
#define CP_COMMIT() asm volatile("cp.async.commit_group;" ::: "memory")
#define CP_WAIT0()  asm volatile("cp.async.wait_group 0;" ::: "memory")

// ============================================================
// Projection GEMM (tf32 mma): q/k[b][n][c] (bf16) = W[c,:]·X[b][:,n] + bias
// Block 128c x 128n, K-chunks 64, cp.async double-buffered.
// ============================================================
#define PROJ_SMEM ((2 * 8704 + 2 * 8704) * 4)

template <int KDIM, int WHICH>
__global__ __launch_bounds__(256) void proj_kernel(const float* __restrict__ W,
                                                   const float* __restrict__ X,
                                                   const float* __restrict__ bias)
{
    extern __shared__ float sm[];
    float* As[2] = { sm, sm + 8704 };                 // [128 m][68 k-pad]
    float* Bs[2] = { sm + 17408, sm + 17408 + 8704 }; // [64 k][136 n-pad]

    const int b  = blockIdx.z;
    const int m0 = blockIdx.y * 128;
    const int n0 = blockIdx.x * 128;
    const int tid = threadIdx.x;
    const int lane = tid & 31, w = tid >> 5;
    const int gid = lane >> 2, tig = lane & 3;
    const int wm = w * 16;
    const int NCH = KDIM / 64;

    float acc[16][4];
    #pragma unroll
    for (int t = 0; t < 16; t++)
        #pragma unroll
        for (int j = 0; j < 4; j++) acc[t][j] = 0.f;

    {
        #pragma unroll
        for (int l = 0; l < 8; l++) {
            int i = tid + l * 256;
            int r = i >> 4, c4 = i & 15;
            CP_A16(smem_u32(As[0] + r * 68 + c4 * 4), W + (size_t)(m0 + r) * KDIM + c4 * 4);
        }
        #pragma unroll
        for (int l = 0; l < 8; l++) {
            int i = tid + l * 256;
            int r = i >> 5, c4 = i & 31;
            CP_A16(smem_u32(Bs[0] + r * 136 + c4 * 4), X + ((size_t)b * KDIM + r) * NN + n0 + c4 * 4);
        }
        CP_COMMIT();
        CP_WAIT0();
        __syncthreads();
    }

    for (int kc = 0; kc < NCH; kc++) {
        const int cur = kc & 1, nxt = cur ^ 1;
        if (kc + 1 < NCH) {
            const int kb = (kc + 1) * 64;
            #pragma unroll
            for (int l = 0; l < 8; l++) {
                int i = tid + l * 256;
                int r = i >> 4, c4 = i & 15;
                CP_A16(smem_u32(As[nxt] + r * 68 + c4 * 4),
                       W + (size_t)(m0 + r) * KDIM + kb + c4 * 4);
            }
            #pragma unroll
            for (int l = 0; l < 8; l++) {
                int i = tid + l * 256;
                int r = i >> 5, c4 = i & 31;
                CP_A16(smem_u32(Bs[nxt] + r * 136 + c4 * 4),
                       X + ((size_t)b * KDIM + kb + r) * NN + n0 + c4 * 4);
            }
        }
        CP_COMMIT();

        const float* Ac = As[cur];
        const float* Bc = Bs[cur];
        #pragma unroll
        for (int ks = 0; ks < 8; ks++) {
            const float* ab = Ac + (wm + gid) * 68 + ks * 8 + tig;
            uint32_t a0 = f2tf32(ab[0]);
            uint32_t a1 = f2tf32(ab[8 * 68]);
            uint32_t a2 = f2tf32(ab[4]);
            uint32_t a3 = f2tf32(ab[8 * 68 + 4]);
            const float* bb = Bc + (ks * 8 + tig) * 136 + gid;
            #pragma unroll
            for (int t = 0; t < 16; t++) {
                uint32_t b0 = f2tf32(bb[t * 8]);
                uint32_t b1 = f2tf32(bb[4 * 136 + t * 8]);
                mma_tf32(acc[t], a0, a1, a2, a3, b0, b1);
            }
        }
        CP_WAIT0();
        __syncthreads();
    }

    // epilogue: + bias, convert bf16, scatter-store transposed [n][c]
    __nv_bfloat16* out = (WHICH == 0) ? g_qh : g_kh;
    const int R0 = m0 + wm + gid;                 // channel
    const float bv0 = bias[R0], bv1 = bias[R0 + 8];
    #pragma unroll
    for (int t = 0; t < 16; t++) {
        int n = n0 + t * 8 + tig * 2;
        __nv_bfloat16* p0 = out + ((size_t)b * NN + n) * CQ;
        __nv_bfloat16* p1 = p0 + CQ;
        p0[R0]     = __float2bfloat16_rn(acc[t][0] + bv0);
        p1[R0]     = __float2bfloat16_rn(acc[t][1] + bv0);
        p0[R0 + 8] = __float2bfloat16_rn(acc[t][2] + bv1);
        p1[R0 + 8] = __float2bfloat16_rn(acc[t][3] + bv1);
    }
}

// ============================================================
// Attention pass 1 (bf16 mma m16n8k16): per (b, 128 m-tile) sweep all n.
// A (q-tile) resident; B (k-tile) double-buffered full-K; S->g_S fp32;
// per-row online (max, sumexp).
// smem rows: 256 bf16 data + 8 pad = 132 u32 pitch.
// ============================================================
#define P1_PITCH 132
#define P1_ASZ   (128 * P1_PITCH)
#define P1_SMEM  (3 * P1_ASZ * 4)

__global__ __launch_bounds__(256) void attn_pass1()
{
    extern __shared__ uint32_t smu[];
    uint32_t* As    = smu;
    uint32_t* Bs[2] = { smu + P1_ASZ, smu + 2 * P1_ASZ };

    const int b  = blockIdx.y;
    const int m0 = blockIdx.x * 128;
    const int tid = threadIdx.x;
    const int lane = tid & 31, w = tid >> 5;
    const int gid = lane >> 2, tig = lane & 3;
    const int wm = w * 16;
    const int R0 = m0 + wm + gid;

    // stage A tile (128 rows x 512B) + B tile 0
    #pragma unroll
    for (int l = 0; l < 16; l++) {
        int i = tid + l * 256;
        int r = i >> 5, c = i & 31;
        CP_A16(smem_u32(As + r * P1_PITCH + c * 4),
               g_qh + ((size_t)b * NN + m0 + r) * CQ + c * 8);
    }
    #pragma unroll
    for (int l = 0; l < 16; l++) {
        int i = tid + l * 256;
        int r = i >> 5, c = i & 31;
        CP_A16(smem_u32(Bs[0] + r * P1_PITCH + c * 4),
               g_kh + ((size_t)b * NN + r) * CQ + c * 8);
    }
    CP_COMMIT();
    CP_WAIT0();
    __syncthreads();

    float run_m0 = -INFINITY, run_m1 = -INFINITY, run_s0 = 0.f, run_s1 = 0.f;

    for (int s = 0; s < 32; s++) {
        const int cur = s & 1, nxt = cur ^ 1;
        if (s + 1 < 32) {
            const __nv_bfloat16* src = g_kh + ((size_t)b * NN + (s + 1) * 128) * CQ;
            #pragma unroll
            for (int l = 0; l < 16; l++) {
                int i = tid + l * 256;
                int r = i >> 5, c = i & 31;
                CP_A16(smem_u32(Bs[nxt] + r * P1_PITCH + c * 4), src + (size_t)r * CQ + c * 8);
            }
        }
        CP_COMMIT();

        float acc[16][4];
        #pragma unroll
        for (int t = 0; t < 16; t++)
            #pragma unroll
            for (int j = 0; j < 4; j++) acc[t][j] = 0.f;

        const uint32_t* Bc = Bs[cur];
        #pragma unroll
        for (int ks = 0; ks < 16; ks++) {
            const uint32_t* ar = As + (wm + gid) * P1_PITCH + ks * 8 + tig;
            uint32_t a0 = ar[0];
            uint32_t a1 = ar[8 * P1_PITCH];
            uint32_t a2 = ar[4];
            uint32_t a3 = ar[8 * P1_PITCH + 4];
            const uint32_t* br = Bc + gid * P1_PITCH + ks * 8 + tig;
            #pragma unroll
            for (int t = 0; t < 16; t++) {
                uint32_t b0 = br[t * 8 * P1_PITCH];
                uint32_t b1 = br[t * 8 * P1_PITCH + 4];
                mma_bf16(acc[t], a0, a1, a2, a3, b0, b1);
            }
        }

        // epilogue: online row stats + S store
        float vm0 = -INFINITY, vm1 = -INFINITY;
        #pragma unroll
        for (int t = 0; t < 16; t++) {
            vm0 = fmaxf(vm0, fmaxf(acc[t][0], acc[t][1]));
            vm1 = fmaxf(vm1, fmaxf(acc[t][2], acc[t][3]));
        }
        vm0 = fmaxf(vm0, __shfl_xor_sync(0xffffffffu, vm0, 1));
        vm0 = fmaxf(vm0, __shfl_xor_sync(0xffffffffu, vm0, 2));
        vm1 = fmaxf(vm1, __shfl_xor_sync(0xffffffffu, vm1, 1));
        vm1 = fmaxf(vm1, __shfl_xor_sync(0xffffffffu, vm1, 2));
        float nm0 = fmaxf(run_m0, vm0);
        float nm1 = fmaxf(run_m1, vm1);
        float s0 = 0.f, s1 = 0.f;
        #pragma unroll
        for (int t = 0; t < 16; t++) {
            s0 += __expf(acc[t][0] - nm0) + __expf(acc[t][1] - nm0);
            s1 += __expf(acc[t][2] - nm1) + __expf(acc[t][3] - nm1);
        }
        s0 += __shfl_xor_sync(0xffffffffu, s0, 1);
        s0 += __shfl_xor_sync(0xffffffffu, s0, 2);
        s1 += __shfl_xor_sync(0xffffffffu, s1, 1);
        s1 += __shfl_xor_sync(0xffffffffu, s1, 2);
        run_s0 = run_s0 * __expf(run_m0 - nm0) + s0;
        run_s1 = run_s1 * __expf(run_m1 - nm1) + s1;
        run_m0 = nm0;
        run_m1 = nm1;

        float* so0 = g_S + ((size_t)b * NN + R0) * NN + s * 128;
        float* so1 = so0 + (size_t)8 * NN;
        #pragma unroll
        for (int t = 0; t < 16; t++) {
            int col = t * 8 + tig * 2;
            *reinterpret_cast<float2*>(so0 + col) = make_float2(acc[t][0], acc[t][1]);
            *reinterpret_cast<float2*>(so1 + col) = make_float2(acc[t][2], acc[t][3]);
        }

        CP_WAIT0();
        __syncthreads();
    }

    if (tig == 0) {
        g_rowmax[b * NN + R0]     = run_m0;
        g_rowsum[b * NN + R0]     = run_s0;
        g_rowmax[b * NN + R0 + 8] = run_m1;
        g_rowsum[b * NN + R0 + 8] = run_s1;
    }
}

// ============================================================
// Attention pass 2: stream S, per-slice column sums. (DRAM-bound, at roofline)
// ============================================================
__global__ __launch_bounds__(256) void attn_pass2()
{
    __shared__ float rm[256], rz[256];
    const int b  = blockIdx.z;
    const int ms = blockIdx.y;
    const int nb = blockIdx.x * 1024;
    const int tid = threadIdx.x;

    rm[tid] = g_rowmax[b * NN + ms * 256 + tid];
    rz[tid] = 1.0f / g_rowsum[b * NN + ms * 256 + tid];
    __syncthreads();

    const float* Sp = g_S + ((size_t)b * NN + ms * 256) * NN + nb + tid * 4;
    float4 acc = make_float4(0.f, 0.f, 0.f, 0.f);
    for (int m = 0; m < 256; m++) {
        float4 s = *reinterpret_cast<const float4*>(Sp + (size_t)m * NN);
        float mx = rm[m], z = rz[m];
        acc.x += __expf(s.x - mx) * z;
        acc.y += __expf(s.y - mx) * z;
        acc.z += __expf(s.z - mx) * z;
        acc.w += __expf(s.w - mx) * z;
    }
    const float sc = 1.0f / NN;
    acc.x *= sc; acc.y *= sc; acc.z *= sc; acc.w *= sc;
    *reinterpret_cast<float4*>(g_wpart + (size_t)ms * (BB * NN) + b * NN + nb + tid * 4) = acc;
}

__global__ void reduce_w_kernel()
{
    const int flat = blockIdx.x * 256 + threadIdx.x;
    float s = 0.f;
    #pragma unroll
    for (int ms = 0; ms < 16; ms++) s += g_wpart[ms * (BB * NN) + flat];
    g_w[flat] = s;
}

// ============================================================
// Weighted/plain reductions over spatial axis
// ============================================================
__global__ void reduce_xw_kernel(const float* __restrict__ img,
                                 const float* __restrict__ pc2d)
{
    const int b = blockIdx.y;
    const int c = blockIdx.x;
    const int t = threadIdx.x;
    const float* wv = g_w + b * NN;
    __shared__ float s1s[4], s2s[4];

    float s1 = 0.f, s2 = 0.f;
    if (c < CQ) {
        const float* row = img + ((size_t)b * CQ + c) * NN;
        for (int n = t; n < NN; n += 128) { float x = row[n]; s1 += x * wv[n]; s2 += x; }
    } else {
        const float* row = pc2d + ((size_t)b * CK + (c - CQ)) * NN;
        for (int n = t; n < NN; n += 128) s1 += row[n] * wv[n];
    }
    #pragma unroll
    for (int o = 16; o; o >>= 1) {
        s1 += __shfl_xor_sync(0xffffffffu, s1, o);
        s2 += __shfl_xor_sync(0xffffffffu, s2, o);
    }
    if ((t & 31) == 0) { s1s[t >> 5] = s1; s2s[t >> 5] = s2; }
    __syncthreads();
    if (t == 0) {
        float a = s1s[0] + s1s[1] + s1s[2] + s1s[3];
        float m = s2s[0] + s2s[1] + s2s[2] + s2s[3];
        if (c < CQ) {
            g_ximg[b * CQ + c] = a;
            g_imgmean[b * CQ + c] = m * (1.0f / NN);
        } else {
            g_xpc[b * CK + (c - CQ)] = a;
        }
    }
}

// ============================================================
// Fused vector
// ============================================================
__global__ void fuse_kernel(const float* __restrict__ Wvi, const float* __restrict__ bvi,
                            const float* __restrict__ Wvp, const float* __restrict__ bvp,
                            const float* __restrict__ gamma1)
{
    const int b = blockIdx.y;
    const int chunk = blockIdx.x;
    const int t = threadIdx.x;
    __shared__ float xs[2048];

    if (chunk == 0) {
        if (t < CQ) xs[t] = g_ximg[b * CQ + t];
        __syncthreads();
        float acc = 0.f;
        const float* wr = Wvi + (size_t)t * CQ;
        for (int i = 0; i < CQ; i++) acc += wr[i] * xs[i];
        float g = gamma1[0];
        g_fused[b * (CQ + CK) + t] = g * (acc + bvi[t]) + g_imgmean[b * CQ + t];
    } else {
        for (int i = t; i < CK; i += 256) xs[i] = g_xpc[b * CK + i];
        __syncthreads();
        int c2 = (chunk - 1) * 256 + t;
        float acc = 0.f;
        const float* wr = Wvp + (size_t)c2 * CK;
        for (int i = 0; i < CK; i++) acc += wr[i] * xs[i];
        g_fused[b * (CQ + CK) + CQ + c2] = acc + bvp[c2];
    }
}

// ============================================================
// MLP head + log_softmax
// ============================================================
__device__ __forceinline__ float warp_red(float v)
{
    #pragma unroll
    for (int o = 16; o; o >>= 1) v += __shfl_xor_sync(0xffffffffu, v, o);
    return v;
}

__global__ void head_kernel(const float* __restrict__ W1, const float* __restrict__ b1,
                            const float* __restrict__ W2, const float* __restrict__ b2,
                            float* __restrict__ out)
{
    const int b = blockIdx.x;
    __shared__ float fs[CQ + CK];
    __shared__ float hs[1024];
    __shared__ float lg[NCLS];
    __shared__ float mxs, lses;
    const int tid = threadIdx.x;
    const int warp = tid >> 5, lane = tid & 31;

    for (int i = tid; i < CQ + CK; i += 256) fs[i] = g_fused[b * (CQ + CK) + i];
    __syncthreads();

    for (int j = warp; j < 1024; j += 8) {
        const float* wr = W1 + (size_t)j * (CQ + CK);
        float s = 0.f;
        for (int i = lane; i < CQ + CK; i += 32) s += fs[i] * wr[i];
        s = warp_red(s);
        if (lane == 0) hs[j] = fmaxf(s + b1[j], 0.f);
    }
    __syncthreads();

    for (int k = warp; k < NCLS; k += 8) {
        const float* wr = W2 + (size_t)k * 1024;
        float s = 0.f;
        for (int i = lane; i < 1024; i += 32) s += hs[i] * wr[i];
        s = warp_red(s);
        if (lane == 0) lg[k] = s + b2[k];
    }
    __syncthreads();

    if (tid == 0) {
        float m = -INFINITY;
        for (int k = 0; k < NCLS; k++) m = fmaxf(m, lg[k]);
        float s = 0.f;
        for (int k = 0; k < NCLS; k++) s += expf(lg[k] - m);
        mxs = m; lses = logf(s);
    }
    __syncthreads();
    if (tid < NCLS) out[b * NCLS + tid] = lg[tid] - mxs - lses;
}

// ============================================================
extern "C" void kernel_launch(void* const* d_in, const int* in_sizes, int n_in,
                              void* d_out, int out_size)
{
    const float* img    = (const float*)d_in[0];
    const float* pc2d   = (const float*)d_in[1];
    const float* Wq     = (const float*)d_in[2];
    const float* bq     = (const float*)d_in[3];
    const float* Wk     = (const float*)d_in[4];
    const float* bk     = (const float*)d_in[5];
    const float* Wvi    = (const float*)d_in[6];
    const float* bvi    = (const float*)d_in[7];
    const float* Wvp    = (const float*)d_in[8];
    const float* bvp    = (const float*)d_in[9];
    const float* gamma1 = (const float*)d_in[10];
    const float* W1     = (const float*)d_in[11];
    const float* b1     = (const float*)d_in[12];
    const float* W2     = (const float*)d_in[13];
    const float* b2     = (const float*)d_in[14];
    float* out = (float*)d_out;

    cudaFuncSetAttribute(proj_kernel<CQ, 0>, cudaFuncAttributeMaxDynamicSharedMemorySize, PROJ_SMEM);
    cudaFuncSetAttribute(proj_kernel<CK, 1>, cudaFuncAttributeMaxDynamicSharedMemorySize, PROJ_SMEM);
    cudaFuncSetAttribute(attn_pass1, cudaFuncAttributeMaxDynamicSharedMemorySize, P1_SMEM);

    dim3 blk(256);
    proj_kernel<CQ, 0><<<dim3(NN / 128, CQ / 128, BB), blk, PROJ_SMEM>>>(Wq, img, bq);
    proj_kernel<CK, 1><<<dim3(NN / 128, CQ / 128, BB), blk, PROJ_SMEM>>>(Wk, pc2d, bk);
    attn_pass1<<<dim3(NN / 128, BB), blk, P1_SMEM>>>();
    attn_pass2<<<dim3(4, 16, BB), blk>>>();
    reduce_w_kernel<<<dim3(BB * NN / 256), blk>>>();
    reduce_xw_kernel<<<dim3(CQ + CK, BB), dim3(128)>>>(img, pc2d);
    fuse_kernel<<<dim3(1 + CK / 256, BB), blk>>>(Wvi, bvi, Wvp, bvp, gamma1);
    head_kernel<<<dim3(BB), blk>>>(W1, b1, W2, b2, out);
}

// round 5
// speedup vs baseline: 7.3570x; 1.0233x over previous
#include <cuda_runtime.h>
#include <cuda_bf16.h>
#include <math.h>
#include <stdint.h>

#define BB 16
#define CQ 256
#define CK 2048
#define NN 4096
#define NCLS 40

// ---- scratch (static __device__ arrays; no allocation) ----
__device__ __nv_bfloat16 g_qh[(size_t)BB * NN * CQ];  // [b][n][c] bf16, 32MB
__device__ __nv_bfloat16 g_kh[(size_t)BB * NN * CQ];  // [b][n][c] bf16, 32MB
__device__ __nv_bfloat16 g_Sh[(size_t)BB * NN * NN];  // [b][m][n] bf16, 536MB
__device__ float g_rowmax[BB * NN];
__device__ float g_rowsum[BB * NN];
__device__ float g_wpart[16 * BB * NN];
__device__ float g_w[BB * NN];
__device__ float g_ximg[BB * CQ];
__device__ float g_imgmean[BB * CQ];
__device__ float g_xpc[BB * CK];
__device__ float g_fused[BB * (CQ + CK)];

// ============================================================
// helpers
// ============================================================
__device__ __forceinline__ uint32_t smem_u32(const void* p) {
    uint32_t a;
    asm("{ .reg .u64 t; cvta.to.shared.u64 t, %1; cvt.u32.u64 %0, t; }" : "=r"(a) : "l"(p));
    return a;
}
__device__ __forceinline__ uint32_t packbf(float x, float y) {
    __nv_bfloat162 h = __floats2bfloat162_rn(x, y);   // x -> low, y -> high
    return *reinterpret_cast<uint32_t*>(&h);
}
__device__ __forceinline__ void mma_bf16(float* c, uint32_t a0, uint32_t a1, uint32_t a2, uint32_t a3,
                                         uint32_t b0, uint32_t b1)
{
    asm volatile(
        "mma.sync.aligned.m16n8k16.row.col.f32.bf16.bf16.f32 "
        "{%0,%1,%2,%3},{%4,%5,%6,%7},{%8,%9},{%0,%1,%2,%3};"
        : "+f"(c[0]), "+f"(c[1]), "+f"(c[2]), "+f"(c[3])
        : "r"(a0), "r"(a1), "r"(a2), "r"(a3), "r"(b0), "r"(b1));
}
#define CP_A16(dst, src) \
    asm volatile("cp.async.ca.shared.global [%0], [%1], 16;" :: "r"(dst), "l"(src))
#define CP_COMMIT() asm volatile("cp.async.commit_group;" ::: "memory")
#define CP_WAIT0()  asm volatile("cp.async.wait_group 0;" ::: "memory")

// ============================================================
// Projection GEMM (bf16 mma m16n8k16): q/k[b][n][c] = W[c,:]·X[b][:,n] + bias
// Block 128c x 128n, k-chunks of 64. bf16 smem staging via registers:
//   A (W) staged [m][k] bf16, B (X) staged TRANSPOSED [n][k] bf16.
// Inner loop: pure LDS.32 + mma (no conversions).
// ============================================================
#define PRJ_PITCH 36                    // u32 per row (64 bf16 data + 8 pad)
#define PRJ_TSZ   (128 * PRJ_PITCH)
#define PROJ_SMEM (4 * PRJ_TSZ * 4)     // 73728 bytes

template <int KDIM, int WHICH>
__global__ __launch_bounds__(256) void proj_kernel(const float* __restrict__ W,
                                                   const float* __restrict__ X,
                                                   const float* __restrict__ bias)
{
    extern __shared__ uint32_t smu[];
    uint32_t* Ab[2] = { smu, smu + PRJ_TSZ };
    uint32_t* Bb[2] = { smu + 2 * PRJ_TSZ, smu + 3 * PRJ_TSZ };

    const int b  = blockIdx.z;
    const int m0 = blockIdx.y * 128;
    const int n0 = blockIdx.x * 128;
    const int tid = threadIdx.x;
    const int lane = tid & 31, w = tid >> 5;
    const int gid = lane >> 2, tig = lane & 3;
    const int wm = w * 16;
    const int NCH = KDIM / 64;
    const float* Xb = X + (size_t)b * KDIM * NN;

    const int am  = tid >> 4, ac4 = tid & 15;   // A task: +16 rows per j
    const int bn  = tid & 127, bkq = tid >> 7;  // B task: +2 kq per j

    float acc[16][4];
    #pragma unroll
    for (int t = 0; t < 16; t++)
        #pragma unroll
        for (int j = 0; j < 4; j++) acc[t][j] = 0.f;

    // ---- stage chunk 0 ----
    #pragma unroll
    for (int j = 0; j < 8; j++) {
        int m = am + j * 16;
        float4 v = *reinterpret_cast<const float4*>(W + (size_t)(m0 + m) * KDIM + ac4 * 4);
        Ab[0][m * PRJ_PITCH + ac4 * 2]     = packbf(v.x, v.y);
        Ab[0][m * PRJ_PITCH + ac4 * 2 + 1] = packbf(v.z, v.w);
    }
    #pragma unroll
    for (int j = 0; j < 8; j++) {
        int kq = bkq + j * 2;
        const float* src = Xb + (size_t)(kq * 4) * NN + n0 + bn;
        float v0 = src[0], v1 = src[NN], v2 = src[2 * (size_t)NN], v3 = src[3 * (size_t)NN];
        Bb[0][bn * PRJ_PITCH + kq * 2]     = packbf(v0, v1);
        Bb[0][bn * PRJ_PITCH + kq * 2 + 1] = packbf(v2, v3);
    }
    __syncthreads();

    for (int kc = 0; kc < NCH; kc++) {
        const int cur = kc & 1, nxt = cur ^ 1;
        float4 ra[8];
        float  rb[8][4];
        if (kc + 1 < NCH) {
            const int kb = (kc + 1) * 64;
            #pragma unroll
            for (int j = 0; j < 8; j++) {
                int m = am + j * 16;
                ra[j] = *reinterpret_cast<const float4*>(W + (size_t)(m0 + m) * KDIM + kb + ac4 * 4);
            }
            #pragma unroll
            for (int j = 0; j < 8; j++) {
                int kq = bkq + j * 2;
                const float* src = Xb + (size_t)(kb + kq * 4) * NN + n0 + bn;
                rb[j][0] = src[0];
                rb[j][1] = src[NN];
                rb[j][2] = src[2 * (size_t)NN];
                rb[j][3] = src[3 * (size_t)NN];
            }
        }

        const uint32_t* Ac = Ab[cur];
        const uint32_t* Bc = Bb[cur];
        #pragma unroll
        for (int ks = 0; ks < 4; ks++) {
            const uint32_t* ar = Ac + (wm + gid) * PRJ_PITCH + ks * 8 + tig;
            uint32_t a0 = ar[0];
            uint32_t a1 = ar[8 * PRJ_PITCH];
            uint32_t a2 = ar[4];
            uint32_t a3 = ar[8 * PRJ_PITCH + 4];
            const uint32_t* br = Bc + gid * PRJ_PITCH + ks * 8 + tig;
            #pragma unroll
            for (int t = 0; t < 16; t++)
                mma_bf16(acc[t], a0, a1, a2, a3,
                         br[t * 8 * PRJ_PITCH], br[t * 8 * PRJ_PITCH + 4]);
        }

        if (kc + 1 < NCH) {
            #pragma unroll
            for (int j = 0; j < 8; j++) {
                int m = am + j * 16;
                Ab[nxt][m * PRJ_PITCH + ac4 * 2]     = packbf(ra[j].x, ra[j].y);
                Ab[nxt][m * PRJ_PITCH + ac4 * 2 + 1] = packbf(ra[j].z, ra[j].w);
            }
            #pragma unroll
            for (int j = 0; j < 8; j++) {
                int kq = bkq + j * 2;
                Bb[nxt][bn * PRJ_PITCH + kq * 2]     = packbf(rb[j][0], rb[j][1]);
                Bb[nxt][bn * PRJ_PITCH + kq * 2 + 1] = packbf(rb[j][2], rb[j][3]);
            }
        }
        __syncthreads();
    }

    // epilogue: + bias, convert bf16, scatter-store transposed [n][c]
    __nv_bfloat16* out = (WHICH == 0) ? g_qh : g_kh;
    const int R0 = m0 + wm + gid;
    const float bv0 = bias[R0], bv1 = bias[R0 + 8];
    #pragma unroll
    for (int t = 0; t < 16; t++) {
        int n = n0 + t * 8 + tig * 2;
        __nv_bfloat16* p0 = out + ((size_t)b * NN + n) * CQ;
        __nv_bfloat16* p1 = p0 + CQ;
        p0[R0]     = __float2bfloat16_rn(acc[t][0] + bv0);
        p1[R0]     = __float2bfloat16_rn(acc[t][1] + bv0);
        p0[R0 + 8] = __float2bfloat16_rn(acc[t][2] + bv1);
        p1[R0 + 8] = __float2bfloat16_rn(acc[t][3] + bv1);
    }
}

// ============================================================
// Attention pass 1 (bf16 mma m16n8k16): per (b, 128 m-tile) sweep all n.
// A (q-tile) resident; B (k-tile) double-buffered; S -> g_Sh (bf16);
// per-row online (max, sumexp) in fp32.
// ============================================================
#define P1_PITCH 132
#define P1_ASZ   (128 * P1_PITCH)
#define P1_SMEM  (3 * P1_ASZ * 4)

__global__ __launch_bounds__(256) void attn_pass1()
{
    extern __shared__ uint32_t smu[];
    uint32_t* As    = smu;
    uint32_t* Bs[2] = { smu + P1_ASZ, smu + 2 * P1_ASZ };

    const int b  = blockIdx.y;
    const int m0 = blockIdx.x * 128;
    const int tid = threadIdx.x;
    const int lane = tid & 31, w = tid >> 5;
    const int gid = lane >> 2, tig = lane & 3;
    const int wm = w * 16;
    const int R0 = m0 + wm + gid;

    #pragma unroll
    for (int l = 0; l < 16; l++) {
        int i = tid + l * 256;
        int r = i >> 5, c = i & 31;
        CP_A16(smem_u32(As + r * P1_PITCH + c * 4),
               g_qh + ((size_t)b * NN + m0 + r) * CQ + c * 8);
    }
    #pragma unroll
    for (int l = 0; l < 16; l++) {
        int i = tid + l * 256;
        int r = i >> 5, c = i & 31;
        CP_A16(smem_u32(Bs[0] + r * P1_PITCH + c * 4),
               g_kh + ((size_t)b * NN + r) * CQ + c * 8);
    }
    CP_COMMIT();
    CP_WAIT0();
    __syncthreads();

    float run_m0 = -INFINITY, run_m1 = -INFINITY, run_s0 = 0.f, run_s1 = 0.f;

    for (int s = 0; s < 32; s++) {
        const int cur = s & 1, nxt = cur ^ 1;
        if (s + 1 < 32) {
            const __nv_bfloat16* src = g_kh + ((size_t)b * NN + (s + 1) * 128) * CQ;
            #pragma unroll
            for (int l = 0; l < 16; l++) {
                int i = tid + l * 256;
                int r = i >> 5, c = i & 31;
                CP_A16(smem_u32(Bs[nxt] + r * P1_PITCH + c * 4), src + (size_t)r * CQ + c * 8);
            }
        }
        CP_COMMIT();

        float acc[16][4];
        #pragma unroll
        for (int t = 0; t < 16; t++)
            #pragma unroll
            for (int j = 0; j < 4; j++) acc[t][j] = 0.f;

        const uint32_t* Bc = Bs[cur];
        #pragma unroll
        for (int ks = 0; ks < 16; ks++) {
            const uint32_t* ar = As + (wm + gid) * P1_PITCH + ks * 8 + tig;
            uint32_t a0 = ar[0];
            uint32_t a1 = ar[8 * P1_PITCH];
            uint32_t a2 = ar[4];
            uint32_t a3 = ar[8 * P1_PITCH + 4];
            const uint32_t* br = Bc + gid * P1_PITCH + ks * 8 + tig;
            #pragma unroll
            for (int t = 0; t < 16; t++) {
                uint32_t b0 = br[t * 8 * P1_PITCH];
                uint32_t b1 = br[t * 8 * P1_PITCH + 4];
                mma_bf16(acc[t], a0, a1, a2, a3, b0, b1);
            }
        }

        // epilogue: online row stats + bf16 S store
        float vm0 = -INFINITY, vm1 = -INFINITY;
        #pragma unroll
        for (int t = 0; t < 16; t++) {
            vm0 = fmaxf(vm0, fmaxf(acc[t][0], acc[t][1]));
            vm1 = fmaxf(vm1, fmaxf(acc[t][2], acc[t][3]));
        }
        vm0 = fmaxf(vm0, __shfl_xor_sync(0xffffffffu, vm0, 1));
        vm0 = fmaxf(vm0, __shfl_xor_sync(0xffffffffu, vm0, 2));
        vm1 = fmaxf(vm1, __shfl_xor_sync(0xffffffffu, vm1, 1));
        vm1 = fmaxf(vm1, __shfl_xor_sync(0xffffffffu, vm1, 2));
        float nm0 = fmaxf(run_m0, vm0);
        float nm1 = fmaxf(run_m1, vm1);
        float s0 = 0.f, s1 = 0.f;
        #pragma unroll
        for (int t = 0; t < 16; t++) {
            s0 += __expf(acc[t][0] - nm0) + __expf(acc[t][1] - nm0);
            s1 += __expf(acc[t][2] - nm1) + __expf(acc[t][3] - nm1);
        }
        s0 += __shfl_xor_sync(0xffffffffu, s0, 1);
        s0 += __shfl_xor_sync(0xffffffffu, s0, 2);
        s1 += __shfl_xor_sync(0xffffffffu, s1, 1);
        s1 += __shfl_xor_sync(0xffffffffu, s1, 2);
        run_s0 = run_s0 * __expf(run_m0 - nm0) + s0;
        run_s1 = run_s1 * __expf(run_m1 - nm1) + s1;
        run_m0 = nm0;
        run_m1 = nm1;

        __nv_bfloat16* so0 = g_Sh + ((size_t)b * NN + R0) * NN + s * 128;
        __nv_bfloat16* so1 = so0 + (size_t)8 * NN;
        #pragma unroll
        for (int t = 0; t < 16; t++) {
            int col = t * 8 + tig * 2;
            *reinterpret_cast<__nv_bfloat162*>(so0 + col) = __floats2bfloat162_rn(acc[t][0], acc[t][1]);
            *reinterpret_cast<__nv_bfloat162*>(so1 + col) = __floats2bfloat162_rn(acc[t][2], acc[t][3]);
        }

        CP_WAIT0();
        __syncthreads();
    }

    if (tig == 0) {
        g_rowmax[b * NN + R0]     = run_m0;
        g_rowsum[b * NN + R0]     = run_s0;
        g_rowmax[b * NN + R0 + 8] = run_m1;
        g_rowsum[b * NN + R0 + 8] = run_s1;
    }
}

// ============================================================
// Attention pass 2: stream bf16 S, per-slice column sums.
// grid (2, 16, B), block 256; thread owns 8 columns.
// ============================================================
__global__ __launch_bounds__(256) void attn_pass2()
{
    __shared__ float rm[256], rz[256];
    const int b  = blockIdx.z;
    const int ms = blockIdx.y;
    const int nb = blockIdx.x * 2048;
    const int tid = threadIdx.x;

    rm[tid] = g_rowmax[b * NN + ms * 256 + tid];
    rz[tid] = 1.0f / g_rowsum[b * NN + ms * 256 + tid];
    __syncthreads();

    const __nv_bfloat16* Sp = g_Sh + ((size_t)b * NN + ms * 256) * NN + nb + tid * 8;
    float a[8];
    #pragma unroll
    for (int i = 0; i < 8; i++) a[i] = 0.f;

    for (int m = 0; m < 256; m++) {
        uint4 r = *reinterpret_cast<const uint4*>(Sp + (size_t)m * NN);
        float mx = rm[m], z = rz[m];
        __nv_bfloat162 p0 = *reinterpret_cast<__nv_bfloat162*>(&r.x);
        __nv_bfloat162 p1 = *reinterpret_cast<__nv_bfloat162*>(&r.y);
        __nv_bfloat162 p2 = *reinterpret_cast<__nv_bfloat162*>(&r.z);
        __nv_bfloat162 p3 = *reinterpret_cast<__nv_bfloat162*>(&r.w);
        a[0] += __expf(__bfloat162float(p0.x) - mx) * z;
        a[1] += __expf(__bfloat162float(p0.y) - mx) * z;
        a[2] += __expf(__bfloat162float(p1.x) - mx) * z;
        a[3] += __expf(__bfloat162float(p1.y) - mx) * z;
        a[4] += __expf(__bfloat162float(p2.x) - mx) * z;
        a[5] += __expf(__bfloat162float(p2.y) - mx) * z;
        a[6] += __expf(__bfloat162float(p3.x) - mx) * z;
        a[7] += __expf(__bfloat162float(p3.y) - mx) * z;
    }
    const float sc = 1.0f / NN;
    float* wp = g_wpart + (size_t)ms * (BB * NN) + b * NN + nb + tid * 8;
    *reinterpret_cast<float4*>(wp)     = make_float4(a[0] * sc, a[1] * sc, a[2] * sc, a[3] * sc);
    *reinterpret_cast<float4*>(wp + 4) = make_float4(a[4] * sc, a[5] * sc, a[6] * sc, a[7] * sc);
}

__global__ void reduce_w_kernel()
{
    const int flat = blockIdx.x * 256 + threadIdx.x;
    float s = 0.f;
    #pragma unroll
    for (int ms = 0; ms < 16; ms++) s += g_wpart[ms * (BB * NN) + flat];
    g_w[flat] = s;
}

// ============================================================
// Weighted/plain reductions over spatial axis
// ============================================================
__global__ void reduce_xw_kernel(const float* __restrict__ img,
                                 const float* __restrict__ pc2d)
{
    const int b = blockIdx.y;
    const int c = blockIdx.x;
    const int t = threadIdx.x;
    const float* wv = g_w + b * NN;
    __shared__ float s1s[4], s2s[4];

    float s1 = 0.f, s2 = 0.f;
    if (c < CQ) {
        const float* row = img + ((size_t)b * CQ + c) * NN;
        for (int n = t; n < NN; n += 128) { float x = row[n]; s1 += x * wv[n]; s2 += x; }
    } else {
        const float* row = pc2d + ((size_t)b * CK + (c - CQ)) * NN;
        for (int n = t; n < NN; n += 128) s1 += row[n] * wv[n];
    }
    #pragma unroll
    for (int o = 16; o; o >>= 1) {
        s1 += __shfl_xor_sync(0xffffffffu, s1, o);
        s2 += __shfl_xor_sync(0xffffffffu, s2, o);
    }
    if ((t & 31) == 0) { s1s[t >> 5] = s1; s2s[t >> 5] = s2; }
    __syncthreads();
    if (t == 0) {
        float a = s1s[0] + s1s[1] + s1s[2] + s1s[3];
        float m = s2s[0] + s2s[1] + s2s[2] + s2s[3];
        if (c < CQ) {
            g_ximg[b * CQ + c] = a;
            g_imgmean[b * CQ + c] = m * (1.0f / NN);
        } else {
            g_xpc[b * CK + (c - CQ)] = a;
        }
    }
}

// ============================================================
// Fused vector
// ============================================================
__global__ void fuse_kernel(const float* __restrict__ Wvi, const float* __restrict__ bvi,
                            const float* __restrict__ Wvp, const float* __restrict__ bvp,
                            const float* __restrict__ gamma1)
{
    const int b = blockIdx.y;
    const int chunk = blockIdx.x;
    const int t = threadIdx.x;
    __shared__ float xs[2048];

    if (chunk == 0) {
        if (t < CQ) xs[t] = g_ximg[b * CQ + t];
        __syncthreads();
        float acc = 0.f;
        const float* wr = Wvi + (size_t)t * CQ;
        for (int i = 0; i < CQ; i++) acc += wr[i] * xs[i];
        float g = gamma1[0];
        g_fused[b * (CQ + CK) + t] = g * (acc + bvi[t]) + g_imgmean[b * CQ + t];
    } else {
        for (int i = t; i < CK; i += 256) xs[i] = g_xpc[b * CK + i];
        __syncthreads();
        int c2 = (chunk - 1) * 256 + t;
        float acc = 0.f;
        const float* wr = Wvp + (size_t)c2 * CK;
        for (int i = 0; i < CK; i++) acc += wr[i] * xs[i];
        g_fused[b * (CQ + CK) + CQ + c2] = acc + bvp[c2];
    }
}

// ============================================================
// MLP head + log_softmax
// ============================================================
__device__ __forceinline__ float warp_red(float v)
{
    #pragma unroll
    for (int o = 16; o; o >>= 1) v += __shfl_xor_sync(0xffffffffu, v, o);
    return v;
}

__global__ void head_kernel(const float* __restrict__ W1, const float* __restrict__ b1,
                            const float* __restrict__ W2, const float* __restrict__ b2,
                            float* __restrict__ out)
{
    const int b = blockIdx.x;
    __shared__ float fs[CQ + CK];
    __shared__ float hs[1024];
    __shared__ float lg[NCLS];
    __shared__ float mxs, lses;
    const int tid = threadIdx.x;
    const int warp = tid >> 5, lane = tid & 31;

    for (int i = tid; i < CQ + CK; i += 256) fs[i] = g_fused[b * (CQ + CK) + i];
    __syncthreads();

    for (int j = warp; j < 1024; j += 8) {
        const float* wr = W1 + (size_t)j * (CQ + CK);
        float s = 0.f;
        for (int i = lane; i < CQ + CK; i += 32) s += fs[i] * wr[i];
        s = warp_red(s);
        if (lane == 0) hs[j] = fmaxf(s + b1[j], 0.f);
    }
    __syncthreads();

    for (int k = warp; k < NCLS; k += 8) {
        const float* wr = W2 + (size_t)k * 1024;
        float s = 0.f;
        for (int i = lane; i < 1024; i += 32) s += hs[i] * wr[i];
        s = warp_red(s);
        if (lane == 0) lg[k] = s + b2[k];
    }
    __syncthreads();

    if (tid == 0) {
        float m = -INFINITY;
        for (int k = 0; k < NCLS; k++) m = fmaxf(m, lg[k]);
        float s = 0.f;
        for (int k = 0; k < NCLS; k++) s += expf(lg[k] - m);
        mxs = m; lses = logf(s);
    }
    __syncthreads();
    if (tid < NCLS) out[b * NCLS + tid] = lg[tid] - mxs - lses;
}

// ============================================================
extern "C" void kernel_launch(void* const* d_in, const int* in_sizes, int n_in,
                              void* d_out, int out_size)
{
    const float* img    = (const float*)d_in[0];
    const float* pc2d   = (const float*)d_in[1];
    const float* Wq     = (const float*)d_in[2];
    const float* bq     = (const float*)d_in[3];
    const float* Wk     = (const float*)d_in[4];
    const float* bk     = (const float*)d_in[5];
    const float* Wvi    = (const float*)d_in[6];
    const float* bvi    = (const float*)d_in[7];
    const float* Wvp    = (const float*)d_in[8];
    const float* bvp    = (const float*)d_in[9];
    const float* gamma1 = (const float*)d_in[10];
    const float* W1     = (const float*)d_in[11];
    const float* b1     = (const float*)d_in[12];
    const float* W2     = (const float*)d_in[13];
    const float* b2     = (const float*)d_in[14];
    float* out = (float*)d_out;

    cudaFuncSetAttribute(proj_kernel<CQ, 0>, cudaFuncAttributeMaxDynamicSharedMemorySize, PROJ_SMEM);
    cudaFuncSetAttribute(proj_kernel<CK, 1>, cudaFuncAttributeMaxDynamicSharedMemorySize, PROJ_SMEM);
    cudaFuncSetAttribute(attn_pass1, cudaFuncAttributeMaxDynamicSharedMemorySize, P1_SMEM);

    dim3 blk(256);
    proj_kernel<CQ, 0><<<dim3(NN / 128, CQ / 128, BB), blk, PROJ_SMEM>>>(Wq, img, bq);
    proj_kernel<CK, 1><<<dim3(NN / 128, CQ / 128, BB), blk, PROJ_SMEM>>>(Wk, pc2d, bk);
    attn_pass1<<<dim3(NN / 128, BB), blk, P1_SMEM>>>();
    attn_pass2<<<dim3(2, 16, BB), blk>>>();
    reduce_w_kernel<<<dim3(BB * NN / 256), blk>>>();
    reduce_xw_kernel<<<dim3(CQ + CK, BB), dim3(128)>>>(img, pc2d);
    fuse_kernel<<<dim3(1 + CK / 256, BB), blk>>>(Wvi, bvi, Wvp, bvp, gamma1);
    head_kernel<<<dim3(BB), blk>>>(W1, b1, W2, b2, out);
}

// round 6
// speedup vs baseline: 7.5873x; 1.0313x over previous
#include <cuda_runtime.h>
#include <cuda_bf16.h>
#include <math.h>
#include <stdint.h>

#define BB 16
#define CQ 256
#define CK 2048
#define NN 4096
#define NCLS 40

// ---- scratch (static __device__ arrays; no allocation) ----
__device__ __nv_bfloat16 g_imgh[(size_t)BB * NN * CQ];  // img  [b][n][c] bf16
__device__ __nv_bfloat16 g_pch[(size_t)BB * NN * CK];   // pc2d [b][n][c] bf16
__device__ __nv_bfloat16 g_wqh[CQ * CQ];
__device__ __nv_bfloat16 g_wkh[CQ * CK];
__device__ __nv_bfloat16 g_qh[(size_t)BB * NN * CQ];    // q [b][n][c] bf16
__device__ __nv_bfloat16 g_kh[(size_t)BB * NN * CQ];    // k [b][n][c] bf16
__device__ __nv_bfloat16 g_Sh[(size_t)BB * NN * NN];    // S [b][m][n] bf16
__device__ float g_rowmax[BB * NN];
__device__ float g_rowsum[BB * NN];
__device__ float g_wpart[32 * BB * NN];
__device__ float g_w[BB * NN];
__device__ float g_ximg[BB * CQ];
__device__ float g_imgmean[BB * CQ];
__device__ float g_xpc[BB * CK];
__device__ float g_fused[BB * (CQ + CK)];

// ============================================================
// helpers
// ============================================================
__device__ __forceinline__ uint32_t smem_u32(const void* p) {
    uint32_t a;
    asm("{ .reg .u64 t; cvta.to.shared.u64 t, %1; cvt.u32.u64 %0, t; }" : "=r"(a) : "l"(p));
    return a;
}
__device__ __forceinline__ void mma_bf16(float* c, uint32_t a0, uint32_t a1, uint32_t a2, uint32_t a3,
                                         uint32_t b0, uint32_t b1)
{
    asm volatile(
        "mma.sync.aligned.m16n8k16.row.col.f32.bf16.bf16.f32 "
        "{%0,%1,%2,%3},{%4,%5,%6,%7},{%8,%9},{%0,%1,%2,%3};"
        : "+f"(c[0]), "+f"(c[1]), "+f"(c[2]), "+f"(c[3])
        : "r"(a0), "r"(a1), "r"(a2), "r"(a3), "r"(b0), "r"(b1));
}
#define CP_A16(dst, src) \
    asm volatile("cp.async.ca.shared.global [%0], [%1], 16;" :: "r"(dst), "l"(src))
#define CP_COMMIT() asm volatile("cp.async.commit_group;" ::: "memory")
#define CP_WAIT0()  asm volatile("cp.async.wait_group 0;" ::: "memory")

// ============================================================
// Transpose-convert: in[b][C][NN] fp32 -> out[b][NN][C] bf16
// 32x32 tiles, block (32,8)
// ============================================================
template <int C>
__global__ __launch_bounds__(256) void cvt_x_kernel(const float* __restrict__ in,
                                                    __nv_bfloat16* __restrict__ out)
{
    __shared__ float t[32][33];
    const int b  = blockIdx.z;
    const int c0 = blockIdx.y * 32;
    const int n0 = blockIdx.x * 32;
    const int tx = threadIdx.x, ty = threadIdx.y;

    const float* ib = in + ((size_t)b * C + c0) * NN + n0;
    #pragma unroll
    for (int i = 0; i < 4; i++) {
        int c = ty + i * 8;
        t[c][tx] = ib[(size_t)c * NN + tx];
    }
    __syncthreads();
    __nv_bfloat16* ob = out + ((size_t)b * NN + n0) * C + c0;
    #pragma unroll
    for (int i = 0; i < 4; i++) {
        int r = ty + i * 8;
        ob[(size_t)r * C + tx] = __float2bfloat16_rn(t[tx][r]);
    }
}

__global__ void cvt_flat_kernel(const float* __restrict__ src,
                                __nv_bfloat16* __restrict__ dst, int n)
{
    int i = blockIdx.x * 256 + threadIdx.x;
    for (; i < n; i += gridDim.x * 256) dst[i] = __float2bfloat16_rn(src[i]);
}

// ============================================================
// Projection GEMM (bf16 mma, cp.async pipeline — pass1 clone):
// out[b][n][m] = W[m,:]·Xh[b][n,:] + bias[m]
// Block 128m x 128n; K-chunk 128; A/B double-buffered.
// ============================================================
#define PJ_PITCH 68                       // u32 pitch (128 bf16 + 8 pad)
#define PJ_TSZ   (128 * PJ_PITCH)
#define PROJ_SMEM (4 * PJ_TSZ * 4)        // 139264 B

template <int KDIM, int WHICH>
__global__ __launch_bounds__(256) void proj_kernel(const __nv_bfloat16* __restrict__ Wh,
                                                   const __nv_bfloat16* __restrict__ Xh,
                                                   const float* __restrict__ bias)
{
    extern __shared__ uint32_t smu[];
    uint32_t* Ab[2] = { smu, smu + PJ_TSZ };
    uint32_t* Bb[2] = { smu + 2 * PJ_TSZ, smu + 3 * PJ_TSZ };

    const int b  = blockIdx.z;
    const int m0 = blockIdx.y * 128;
    const int n0 = blockIdx.x * 128;
    const int tid = threadIdx.x;
    const int lane = tid & 31, w = tid >> 5;
    const int gid = lane >> 2, tig = lane & 3;
    const int wm = w * 16;
    const int NCH = KDIM / 128;
    const __nv_bfloat16* Xb = Xh + (size_t)b * NN * KDIM + (size_t)n0 * KDIM;

    float acc[16][4];
    #pragma unroll
    for (int t = 0; t < 16; t++)
        #pragma unroll
        for (int j = 0; j < 4; j++) acc[t][j] = 0.f;

    // stage chunk 0: A rows 256B, B rows 256B
    #pragma unroll
    for (int l = 0; l < 8; l++) {
        int i = tid + l * 256;
        int r = i >> 4, c = i & 15;
        CP_A16(smem_u32(Ab[0] + r * PJ_PITCH + c * 4), Wh + (size_t)(m0 + r) * KDIM + c * 8);
    }
    #pragma unroll
    for (int l = 0; l < 8; l++) {
        int i = tid + l * 256;
        int r = i >> 4, c = i & 15;
        CP_A16(smem_u32(Bb[0] + r * PJ_PITCH + c * 4), Xb + (size_t)r * KDIM + c * 8);
    }
    CP_COMMIT();
    CP_WAIT0();
    __syncthreads();

    for (int kc = 0; kc < NCH; kc++) {
        const int cur = kc & 1, nxt = cur ^ 1;
        if (kc + 1 < NCH) {
            const int kb = (kc + 1) * 128;
            #pragma unroll
            for (int l = 0; l < 8; l++) {
                int i = tid + l * 256;
                int r = i >> 4, c = i & 15;
                CP_A16(smem_u32(Ab[nxt] + r * PJ_PITCH + c * 4),
                       Wh + (size_t)(m0 + r) * KDIM + kb + c * 8);
            }
            #pragma unroll
            for (int l = 0; l < 8; l++) {
                int i = tid + l * 256;
                int r = i >> 4, c = i & 15;
                CP_A16(smem_u32(Bb[nxt] + r * PJ_PITCH + c * 4),
                       Xb + (size_t)r * KDIM + kb + c * 8);
            }
        }
        CP_COMMIT();

        const uint32_t* Ac = Ab[cur];
        const uint32_t* Bc = Bb[cur];
        #pragma unroll
        for (int ks = 0; ks < 8; ks++) {
            const uint32_t* ar = Ac + (wm + gid) * PJ_PITCH + ks * 8 + tig;
            uint32_t a0 = ar[0];
            uint32_t a1 = ar[8 * PJ_PITCH];
            uint32_t a2 = ar[4];
            uint32_t a3 = ar[8 * PJ_PITCH + 4];
            const uint32_t* br = Bc + gid * PJ_PITCH + ks * 8 + tig;
            #pragma unroll
            for (int t = 0; t < 16; t++)
                mma_bf16(acc[t], a0, a1, a2, a3,
                         br[t * 8 * PJ_PITCH], br[t * 8 * PJ_PITCH + 4]);
        }
        CP_WAIT0();
        __syncthreads();
    }

    // epilogue: + bias, bf16, scatter-store [n][m]
    __nv_bfloat16* out = (WHICH == 0) ? g_qh : g_kh;
    const int R0 = m0 + wm + gid;
    const float bv0 = bias[R0], bv1 = bias[R0 + 8];
    #pragma unroll
    for (int t = 0; t < 16; t++) {
        int n = n0 + t * 8 + tig * 2;
        __nv_bfloat16* p0 = out + ((size_t)b * NN + n) * CQ;
        __nv_bfloat16* p1 = p0 + CQ;
        p0[R0]     = __float2bfloat16_rn(acc[t][0] + bv0);
        p1[R0]     = __float2bfloat16_rn(acc[t][1] + bv0);
        p0[R0 + 8] = __float2bfloat16_rn(acc[t][2] + bv1);
        p1[R0 + 8] = __float2bfloat16_rn(acc[t][3] + bv1);
    }
}

// ============================================================
// Attention pass 1 (bf16 mma): per (b, 128 m-tile) sweep all n.
// A resident; B double-buffered; S -> g_Sh bf16; online row stats fp32.
// ============================================================
#define P1_PITCH 132
#define P1_ASZ   (128 * P1_PITCH)
#define P1_SMEM  (3 * P1_ASZ * 4)

__global__ __launch_bounds__(256) void attn_pass1()
{
    extern __shared__ uint32_t smu[];
    uint32_t* As    = smu;
    uint32_t* Bs[2] = { smu + P1_ASZ, smu + 2 * P1_ASZ };

    const int b  = blockIdx.y;
    const int m0 = blockIdx.x * 128;
    const int tid = threadIdx.x;
    const int lane = tid & 31, w = tid >> 5;
    const int gid = lane >> 2, tig = lane & 3;
    const int wm = w * 16;
    const int R0 = m0 + wm + gid;

    #pragma unroll
    for (int l = 0; l < 16; l++) {
        int i = tid + l * 256;
        int r = i >> 5, c = i & 31;
        CP_A16(smem_u32(As + r * P1_PITCH + c * 4),
               g_qh + ((size_t)b * NN + m0 + r) * CQ + c * 8);
    }
    #pragma unroll
    for (int l = 0; l < 16; l++) {
        int i = tid + l * 256;
        int r = i >> 5, c = i & 31;
        CP_A16(smem_u32(Bs[0] + r * P1_PITCH + c * 4),
               g_kh + ((size_t)b * NN + r) * CQ + c * 8);
    }
    CP_COMMIT();
    CP_WAIT0();
    __syncthreads();

    float run_m0 = -INFINITY, run_m1 = -INFINITY, run_s0 = 0.f, run_s1 = 0.f;

    for (int s = 0; s < 32; s++) {
        const int cur = s & 1, nxt = cur ^ 1;
        if (s + 1 < 32) {
            const __nv_bfloat16* src = g_kh + ((size_t)b * NN + (s + 1) * 128) * CQ;
            #pragma unroll
            for (int l = 0; l < 16; l++) {
                int i = tid + l * 256;
                int r = i >> 5, c = i & 31;
                CP_A16(smem_u32(Bs[nxt] + r * P1_PITCH + c * 4), src + (size_t)r * CQ + c * 8);
            }
        }
        CP_COMMIT();

        float acc[16][4];
        #pragma unroll
        for (int t = 0; t < 16; t++)
            #pragma unroll
            for (int j = 0; j < 4; j++) acc[t][j] = 0.f;

        const uint32_t* Bc = Bs[cur];
        #pragma unroll
        for (int ks = 0; ks < 16; ks++) {
            const uint32_t* ar = As + (wm + gid) * P1_PITCH + ks * 8 + tig;
            uint32_t a0 = ar[0];
            uint32_t a1 = ar[8 * P1_PITCH];
            uint32_t a2 = ar[4];
            uint32_t a3 = ar[8 * P1_PITCH + 4];
            const uint32_t* br = Bc + gid * P1_PITCH + ks * 8 + tig;
            #pragma unroll
            for (int t = 0; t < 16; t++) {
                uint32_t b0 = br[t * 8 * P1_PITCH];
                uint32_t b1 = br[t * 8 * P1_PITCH + 4];
                mma_bf16(acc[t], a0, a1, a2, a3, b0, b1);
            }
        }

        float vm0 = -INFINITY, vm1 = -INFINITY;
        #pragma unroll
        for (int t = 0; t < 16; t++) {
            vm0 = fmaxf(vm0, fmaxf(acc[t][0], acc[t][1]));
            vm1 = fmaxf(vm1, fmaxf(acc[t][2], acc[t][3]));
        }
        vm0 = fmaxf(vm0, __shfl_xor_sync(0xffffffffu, vm0, 1));
        vm0 = fmaxf(vm0, __shfl_xor_sync(0xffffffffu, vm0, 2));
        vm1 = fmaxf(vm1, __shfl_xor_sync(0xffffffffu, vm1, 1));
        vm1 = fmaxf(vm1, __shfl_xor_sync(0xffffffffu, vm1, 2));
        float nm0 = fmaxf(run_m0, vm0);
        float nm1 = fmaxf(run_m1, vm1);
        float s0 = 0.f, s1 = 0.f;
        #pragma unroll
        for (int t = 0; t < 16; t++) {
            s0 += __expf(acc[t][0] - nm0) + __expf(acc[t][1] - nm0);
            s1 += __expf(acc[t][2] - nm1) + __expf(acc[t][3] - nm1);
        }
        s0 += __shfl_xor_sync(0xffffffffu, s0, 1);
        s0 += __shfl_xor_sync(0xffffffffu, s0, 2);
        s1 += __shfl_xor_sync(0xffffffffu, s1, 1);
        s1 += __shfl_xor_sync(0xffffffffu, s1, 2);
        run_s0 = run_s0 * __expf(run_m0 - nm0) + s0;
        run_s1 = run_s1 * __expf(run_m1 - nm1) + s1;
        run_m0 = nm0;
        run_m1 = nm1;

        __nv_bfloat16* so0 = g_Sh + ((size_t)b * NN + R0) * NN + s * 128;
        __nv_bfloat16* so1 = so0 + (size_t)8 * NN;
        #pragma unroll
        for (int t = 0; t < 16; t++) {
            int col = t * 8 + tig * 2;
            *reinterpret_cast<__nv_bfloat162*>(so0 + col) = __floats2bfloat162_rn(acc[t][0], acc[t][1]);
            *reinterpret_cast<__nv_bfloat162*>(so1 + col) = __floats2bfloat162_rn(acc[t][2], acc[t][3]);
        }

        CP_WAIT0();
        __syncthreads();
    }

    if (tig == 0) {
        g_rowmax[b * NN + R0]     = run_m0;
        g_rowsum[b * NN + R0]     = run_s0;
        g_rowmax[b * NN + R0 + 8] = run_m1;
        g_rowsum[b * NN + R0 + 8] = run_s1;
    }
}

// ============================================================
// Attention pass 2: stream bf16 S, per-slice column sums.
// grid (2, 32, B), block 256; thread owns 8 columns, 128 m-rows/slice.
// ============================================================
__global__ __launch_bounds__(256) void attn_pass2()
{
    __shared__ float rm[128], rz[128];
    const int b  = blockIdx.z;
    const int ms = blockIdx.y;
    const int nb = blockIdx.x * 2048;
    const int tid = threadIdx.x;

    if (tid < 128) {
        rm[tid] = g_rowmax[b * NN + ms * 128 + tid];
        rz[tid] = 1.0f / g_rowsum[b * NN + ms * 128 + tid];
    }
    __syncthreads();

    const __nv_bfloat16* Sp = g_Sh + ((size_t)b * NN + ms * 128) * NN + nb + tid * 8;
    float a[8];
    #pragma unroll
    for (int i = 0; i < 8; i++) a[i] = 0.f;

    for (int m = 0; m < 128; m++) {
        uint4 r = *reinterpret_cast<const uint4*>(Sp + (size_t)m * NN);
        float mx = rm[m], z = rz[m];
        __nv_bfloat162 p0 = *reinterpret_cast<__nv_bfloat162*>(&r.x);
        __nv_bfloat162 p1 = *reinterpret_cast<__nv_bfloat162*>(&r.y);
        __nv_bfloat162 p2 = *reinterpret_cast<__nv_bfloat162*>(&r.z);
        __nv_bfloat162 p3 = *reinterpret_cast<__nv_bfloat162*>(&r.w);
        a[0] += __expf(__bfloat162float(p0.x) - mx) * z;
        a[1] += __expf(__bfloat162float(p0.y) - mx) * z;
        a[2] += __expf(__bfloat162float(p1.x) - mx) * z;
        a[3] += __expf(__bfloat162float(p1.y) - mx) * z;
        a[4] += __expf(__bfloat162float(p2.x) - mx) * z;
        a[5] += __expf(__bfloat162float(p2.y) - mx) * z;
        a[6] += __expf(__bfloat162float(p3.x) - mx) * z;
        a[7] += __expf(__bfloat162float(p3.y) - mx) * z;
    }
    const float sc = 1.0f / NN;
    float* wp = g_wpart + (size_t)ms * (BB * NN) + b * NN + nb + tid * 8;
    *reinterpret_cast<float4*>(wp)     = make_float4(a[0] * sc, a[1] * sc, a[2] * sc, a[3] * sc);
    *reinterpret_cast<float4*>(wp + 4) = make_float4(a[4] * sc, a[5] * sc, a[6] * sc, a[7] * sc);
}

__global__ void reduce_w_kernel()
{
    const int flat = blockIdx.x * 256 + threadIdx.x;
    float s = 0.f;
    #pragma unroll
    for (int ms = 0; ms < 32; ms++) s += g_wpart[ms * (BB * NN) + flat];
    g_w[flat] = s;
}

// ============================================================
// Weighted/plain reductions over spatial axis
// ============================================================
__global__ void reduce_xw_kernel(const float* __restrict__ img,
                                 const float* __restrict__ pc2d)
{
    const int b = blockIdx.y;
    const int c = blockIdx.x;
    const int t = threadIdx.x;
    const float* wv = g_w + b * NN;
    __shared__ float s1s[4], s2s[4];

    float s1 = 0.f, s2 = 0.f;
    if (c < CQ) {
        const float* row = img + ((size_t)b * CQ + c) * NN;
        for (int n = t; n < NN; n += 128) { float x = row[n]; s1 += x * wv[n]; s2 += x; }
    } else {
        const float* row = pc2d + ((size_t)b * CK + (c - CQ)) * NN;
        for (int n = t; n < NN; n += 128) s1 += row[n] * wv[n];
    }
    #pragma unroll
    for (int o = 16; o; o >>= 1) {
        s1 += __shfl_xor_sync(0xffffffffu, s1, o);
        s2 += __shfl_xor_sync(0xffffffffu, s2, o);
    }
    if ((t & 31) == 0) { s1s[t >> 5] = s1; s2s[t >> 5] = s2; }
    __syncthreads();
    if (t == 0) {
        float a = s1s[0] + s1s[1] + s1s[2] + s1s[3];
        float m = s2s[0] + s2s[1] + s2s[2] + s2s[3];
        if (c < CQ) {
            g_ximg[b * CQ + c] = a;
            g_imgmean[b * CQ + c] = m * (1.0f / NN);
        } else {
            g_xpc[b * CK + (c - CQ)] = a;
        }
    }
}

// ============================================================
// Fused vector
// ============================================================
__global__ void fuse_kernel(const float* __restrict__ Wvi, const float* __restrict__ bvi,
                            const float* __restrict__ Wvp, const float* __restrict__ bvp,
                            const float* __restrict__ gamma1)
{
    const int b = blockIdx.y;
    const int chunk = blockIdx.x;
    const int t = threadIdx.x;
    __shared__ float xs[2048];

    if (chunk == 0) {
        if (t < CQ) xs[t] = g_ximg[b * CQ + t];
        __syncthreads();
        float acc = 0.f;
        const float* wr = Wvi + (size_t)t * CQ;
        for (int i = 0; i < CQ; i++) acc += wr[i] * xs[i];
        float g = gamma1[0];
        g_fused[b * (CQ + CK) + t] = g * (acc + bvi[t]) + g_imgmean[b * CQ + t];
    } else {
        for (int i = t; i < CK; i += 256) xs[i] = g_xpc[b * CK + i];
        __syncthreads();
        int c2 = (chunk - 1) * 256 + t;
        float acc = 0.f;
        const float* wr = Wvp + (size_t)c2 * CK;
        for (int i = 0; i < CK; i++) acc += wr[i] * xs[i];
        g_fused[b * (CQ + CK) + CQ + c2] = acc + bvp[c2];
    }
}

// ============================================================
// MLP head + log_softmax
// ============================================================
__device__ __forceinline__ float warp_red(float v)
{
    #pragma unroll
    for (int o = 16; o; o >>= 1) v += __shfl_xor_sync(0xffffffffu, v, o);
    return v;
}

__global__ void head_kernel(const float* __restrict__ W1, const float* __restrict__ b1,
                            const float* __restrict__ W2, const float* __restrict__ b2,
                            float* __restrict__ out)
{
    const int b = blockIdx.x;
    __shared__ float fs[CQ + CK];
    __shared__ float hs[1024];
    __shared__ float lg[NCLS];
    __shared__ float mxs, lses;
    const int tid = threadIdx.x;
    const int warp = tid >> 5, lane = tid & 31;

    for (int i = tid; i < CQ + CK; i += 256) fs[i] = g_fused[b * (CQ + CK) + i];
    __syncthreads();

    for (int j = warp; j < 1024; j += 8) {
        const float* wr = W1 + (size_t)j * (CQ + CK);
        float s = 0.f;
        for (int i = lane; i < CQ + CK; i += 32) s += fs[i] * wr[i];
        s = warp_red(s);
        if (lane == 0) hs[j] = fmaxf(s + b1[j], 0.f);
    }
    __syncthreads();

    for (int k = warp; k < NCLS; k += 8) {
        const float* wr = W2 + (size_t)k * 1024;
        float s = 0.f;
        for (int i = lane; i < 1024; i += 32) s += hs[i] * wr[i];
        s = warp_red(s);
        if (lane == 0) lg[k] = s + b2[k];
    }
    __syncthreads();

    if (tid == 0) {
        float m = -INFINITY;
        for (int k = 0; k < NCLS; k++) m = fmaxf(m, lg[k]);
        float s = 0.f;
        for (int k = 0; k < NCLS; k++) s += expf(lg[k] - m);
        mxs = m; lses = logf(s);
    }
    __syncthreads();
    if (tid < NCLS) out[b * NCLS + tid] = lg[tid] - mxs - lses;
}

// ============================================================
extern "C" void kernel_launch(void* const* d_in, const int* in_sizes, int n_in,
                              void* d_out, int out_size)
{
    const float* img    = (const float*)d_in[0];
    const float* pc2d   = (const float*)d_in[1];
    const float* Wq     = (const float*)d_in[2];
    const float* bq     = (const float*)d_in[3];
    const float* Wk     = (const float*)d_in[4];
    const float* bk     = (const float*)d_in[5];
    const float* Wvi    = (const float*)d_in[6];
    const float* bvi    = (const float*)d_in[7];
    const float* Wvp    = (const float*)d_in[8];
    const float* bvp    = (const float*)d_in[9];
    const float* gamma1 = (const float*)d_in[10];
    const float* W1     = (const float*)d_in[11];
    const float* b1     = (const float*)d_in[12];
    const float* W2     = (const float*)d_in[13];
    const float* b2     = (const float*)d_in[14];
    float* out = (float*)d_out;

    cudaFuncSetAttribute(proj_kernel<CQ, 0>, cudaFuncAttributeMaxDynamicSharedMemorySize, PROJ_SMEM);
    cudaFuncSetAttribute(proj_kernel<CK, 1>, cudaFuncAttributeMaxDynamicSharedMemorySize, PROJ_SMEM);
    cudaFuncSetAttribute(attn_pass1, cudaFuncAttributeMaxDynamicSharedMemorySize, P1_SMEM);

    __nv_bfloat16* d_imgh = nullptr; cudaGetSymbolAddress((void**)&d_imgh, g_imgh);
    __nv_bfloat16* d_pch  = nullptr; cudaGetSymbolAddress((void**)&d_pch,  g_pch);
    __nv_bfloat16* d_wqh  = nullptr; cudaGetSymbolAddress((void**)&d_wqh,  g_wqh);
    __nv_bfloat16* d_wkh  = nullptr; cudaGetSymbolAddress((void**)&d_wkh,  g_wkh);

    dim3 blk(256);
    // bf16 transposed inputs + weights
    cvt_x_kernel<CQ><<<dim3(NN / 32, CQ / 32, BB), dim3(32, 8)>>>(img, d_imgh);
    cvt_x_kernel<CK><<<dim3(NN / 32, CK / 32, BB), dim3(32, 8)>>>(pc2d, d_pch);
    cvt_flat_kernel<<<64, blk>>>(Wq, d_wqh, CQ * CQ);
    cvt_flat_kernel<<<256, blk>>>(Wk, d_wkh, CQ * CK);
    // projections (bf16 tensor pipeline)
    proj_kernel<CQ, 0><<<dim3(NN / 128, CQ / 128, BB), blk, PROJ_SMEM>>>(d_wqh, d_imgh, bq);
    proj_kernel<CK, 1><<<dim3(NN / 128, CQ / 128, BB), blk, PROJ_SMEM>>>(d_wkh, d_pch, bk);
    // attention
    attn_pass1<<<dim3(NN / 128, BB), blk, P1_SMEM>>>();
    attn_pass2<<<dim3(2, 32, BB), blk>>>();
    reduce_w_kernel<<<dim3(BB * NN / 256), blk>>>();
    // tail
    reduce_xw_kernel<<<dim3(CQ + CK, BB), dim3(128)>>>(img, pc2d);
    fuse_kernel<<<dim3(1 + CK / 256, BB), blk>>>(Wvi, bvi, Wvp, bvp, gamma1);
    head_kernel<<<dim3(BB), blk>>>(W1, b1, W2, b2, out);
}

// round 7
// speedup vs baseline: 8.7508x; 1.1533x over previous
#include <cuda_runtime.h>
#include <cuda_bf16.h>
#include <math.h>
#include <stdint.h>

#define BB 16
#define CQ 256
#define CK 2048
#define NN 4096
#define NCLS 40

// ---- scratch (static __device__ arrays; no allocation) ----
__device__ __nv_bfloat16 g_imgh[(size_t)BB * NN * CQ];  // img  [b][n][c] bf16
__device__ __nv_bfloat16 g_pch[(size_t)BB * NN * CK];   // pc2d [b][n][c] bf16
__device__ __nv_bfloat16 g_wqh[CQ * CQ];
__device__ __nv_bfloat16 g_wkh[CQ * CK];
__device__ __nv_bfloat16 g_qh[(size_t)BB * NN * CQ];    // q [b][n][c] bf16
__device__ __nv_bfloat16 g_kh[(size_t)BB * NN * CQ];    // k [b][n][c] bf16
__device__ __nv_bfloat16 g_Sh[(size_t)BB * NN * NN];    // S [b][m][n] bf16
__device__ float g_rowmax[BB * NN];
__device__ float g_rowsum[BB * NN];
__device__ float g_wpart[32 * BB * NN];
__device__ float g_w[BB * NN];
__device__ float g_ximg[BB * CQ];
__device__ float g_imgmean[BB * CQ];
__device__ float g_xpc[BB * CK];
__device__ float g_fused[BB * (CQ + CK)];

// ============================================================
// helpers
// ============================================================
__device__ __forceinline__ uint32_t smem_u32(const void* p) {
    uint32_t a;
    asm("{ .reg .u64 t; cvta.to.shared.u64 t, %1; cvt.u32.u64 %0, t; }" : "=r"(a) : "l"(p));
    return a;
}
__device__ __forceinline__ void mma_bf16(float* c, uint32_t a0, uint32_t a1, uint32_t a2, uint32_t a3,
                                         uint32_t b0, uint32_t b1)
{
    asm volatile(
        "mma.sync.aligned.m16n8k16.row.col.f32.bf16.bf16.f32 "
        "{%0,%1,%2,%3},{%4,%5,%6,%7},{%8,%9},{%0,%1,%2,%3};"
        : "+f"(c[0]), "+f"(c[1]), "+f"(c[2]), "+f"(c[3])
        : "r"(a0), "r"(a1), "r"(a2), "r"(a3), "r"(b0), "r"(b1));
}
__device__ __forceinline__ void ldm_x4(uint32_t* r, uint32_t addr)
{
    asm volatile("ldmatrix.sync.aligned.m8n8.x4.shared.b16 {%0,%1,%2,%3}, [%4];"
        : "=r"(r[0]), "=r"(r[1]), "=r"(r[2]), "=r"(r[3]) : "r"(addr));
}
#define CP_A16(dst, src) \
    asm volatile("cp.async.ca.shared.global [%0], [%1], 16;" :: "r"(dst), "l"(src))
#define CP_COMMIT() asm volatile("cp.async.commit_group;" ::: "memory")
#define CP_WAIT0()  asm volatile("cp.async.wait_group 0;" ::: "memory")

// per-lane ldmatrix address offsets (u32 units), PITCH templated
// A: row = base_m + (lane&15), colsel = (lane&16)?4:0
// B: row = (lane&7) + ((lane&16)>>1), colsel = (lane&8)?4:0
//   x4 regs -> {b0_t0, b1_t0, b0_t1, b1_t1} for two n-tiles of 8

// ============================================================
// Transpose-convert: in[b][C][NN] fp32 -> out[b][NN][C] bf16
// ============================================================
template <int C>
__global__ __launch_bounds__(256) void cvt_x_kernel(const float* __restrict__ in,
                                                    __nv_bfloat16* __restrict__ out)
{
    __shared__ float t[32][33];
    const int b  = blockIdx.z;
    const int c0 = blockIdx.y * 32;
    const int n0 = blockIdx.x * 32;
    const int tx = threadIdx.x, ty = threadIdx.y;

    const float* ib = in + ((size_t)b * C + c0) * NN + n0;
    #pragma unroll
    for (int i = 0; i < 4; i++) {
        int c = ty + i * 8;
        t[c][tx] = ib[(size_t)c * NN + tx];
    }
    __syncthreads();
    __nv_bfloat16* ob = out + ((size_t)b * NN + n0) * C + c0;
    #pragma unroll
    for (int i = 0; i < 4; i++) {
        int r = ty + i * 8;
        ob[(size_t)r * C + tx] = __float2bfloat16_rn(t[tx][r]);
    }
}

__global__ void cvt_wqk_kernel(const float* __restrict__ Wq, const float* __restrict__ Wk)
{
    const int total = CQ * CQ + CQ * CK;
    int i = blockIdx.x * 256 + threadIdx.x;
    for (; i < total; i += gridDim.x * 256) {
        if (i < CQ * CQ) g_wqh[i] = __float2bfloat16_rn(Wq[i]);
        else             g_wkh[i - CQ * CQ] = __float2bfloat16_rn(Wk[i - CQ * CQ]);
    }
}

// ============================================================
// Projection GEMM (bf16 mma + ldmatrix): out[b][n][m] = W[m,:]·Xh[b][n,:]+bias
// Block 128m x 128n; K-chunk 128; A/B double-buffered.
// ============================================================
#define PJ_PITCH 68
#define PJ_TSZ   (128 * PJ_PITCH)
#define PROJ_SMEM (4 * PJ_TSZ * 4)

template <int KDIM, int WHICH>
__global__ __launch_bounds__(256) void proj_kernel(const __nv_bfloat16* __restrict__ Wh,
                                                   const __nv_bfloat16* __restrict__ Xh,
                                                   const float* __restrict__ bias)
{
    extern __shared__ uint32_t smu[];
    uint32_t* Ab[2] = { smu, smu + PJ_TSZ };
    uint32_t* Bb[2] = { smu + 2 * PJ_TSZ, smu + 3 * PJ_TSZ };

    const int b  = blockIdx.z;
    const int m0 = blockIdx.y * 128;
    const int n0 = blockIdx.x * 128;
    const int tid = threadIdx.x;
    const int lane = tid & 31, w = tid >> 5;
    const int gid = lane >> 2, tig = lane & 3;
    const int wm = w * 16;
    const int NCH = KDIM / 128;
    const __nv_bfloat16* Xb = Xh + (size_t)b * NN * KDIM + (size_t)n0 * KDIM;

    const uint32_t sbase = smem_u32(smu);
    const uint32_t aoff = ((wm + (lane & 15)) * PJ_PITCH + ((lane & 16) ? 4 : 0)) * 4;
    const uint32_t boff = (((lane & 7) + ((lane & 16) >> 1)) * PJ_PITCH + ((lane & 8) ? 4 : 0)) * 4;

    float acc[16][4];
    #pragma unroll
    for (int t = 0; t < 16; t++)
        #pragma unroll
        for (int j = 0; j < 4; j++) acc[t][j] = 0.f;

    #pragma unroll
    for (int l = 0; l < 8; l++) {
        int i = tid + l * 256;
        int r = i >> 4, c = i & 15;
        CP_A16(smem_u32(Ab[0] + r * PJ_PITCH + c * 4), Wh + (size_t)(m0 + r) * KDIM + c * 8);
    }
    #pragma unroll
    for (int l = 0; l < 8; l++) {
        int i = tid + l * 256;
        int r = i >> 4, c = i & 15;
        CP_A16(smem_u32(Bb[0] + r * PJ_PITCH + c * 4), Xb + (size_t)r * KDIM + c * 8);
    }
    CP_COMMIT();
    CP_WAIT0();
    __syncthreads();

    for (int kc = 0; kc < NCH; kc++) {
        const int cur = kc & 1, nxt = cur ^ 1;
        if (kc + 1 < NCH) {
            const int kb = (kc + 1) * 128;
            #pragma unroll
            for (int l = 0; l < 8; l++) {
                int i = tid + l * 256;
                int r = i >> 4, c = i & 15;
                CP_A16(smem_u32(Ab[nxt] + r * PJ_PITCH + c * 4),
                       Wh + (size_t)(m0 + r) * KDIM + kb + c * 8);
            }
            #pragma unroll
            for (int l = 0; l < 8; l++) {
                int i = tid + l * 256;
                int r = i >> 4, c = i & 15;
                CP_A16(smem_u32(Bb[nxt] + r * PJ_PITCH + c * 4),
                       Xb + (size_t)r * KDIM + kb + c * 8);
            }
        }
        CP_COMMIT();

        const uint32_t abase = sbase + (uint32_t)(cur * PJ_TSZ) * 4 + aoff;
        const uint32_t bbase = sbase + (uint32_t)((2 + cur) * PJ_TSZ) * 4 + boff;
        #pragma unroll
        for (int ks = 0; ks < 8; ks++) {
            uint32_t a[4];
            ldm_x4(a, abase + ks * 32);
            #pragma unroll
            for (int j = 0; j < 8; j++) {
                uint32_t bf[4];
                ldm_x4(bf, bbase + (uint32_t)(j * 16 * PJ_PITCH) * 4 + ks * 32);
                mma_bf16(acc[2 * j],     a[0], a[1], a[2], a[3], bf[0], bf[1]);
                mma_bf16(acc[2 * j + 1], a[0], a[1], a[2], a[3], bf[2], bf[3]);
            }
        }
        CP_WAIT0();
        __syncthreads();
    }

    __nv_bfloat16* out = (WHICH == 0) ? g_qh : g_kh;
    const int R0 = m0 + wm + gid;
    const float bv0 = bias[R0], bv1 = bias[R0 + 8];
    #pragma unroll
    for (int t = 0; t < 16; t++) {
        int n = n0 + t * 8 + tig * 2;
        __nv_bfloat16* p0 = out + ((size_t)b * NN + n) * CQ;
        __nv_bfloat16* p1 = p0 + CQ;
        p0[R0]     = __float2bfloat16_rn(acc[t][0] + bv0);
        p1[R0]     = __float2bfloat16_rn(acc[t][1] + bv0);
        p0[R0 + 8] = __float2bfloat16_rn(acc[t][2] + bv1);
        p1[R0 + 8] = __float2bfloat16_rn(acc[t][3] + bv1);
    }
}

// ============================================================
// Attention pass 1 (bf16 mma + ldmatrix): per (b, 128 m-tile) sweep all n.
// ============================================================
#define P1_PITCH 132
#define P1_ASZ   (128 * P1_PITCH)
#define P1_SMEM  (3 * P1_ASZ * 4)

__global__ __launch_bounds__(256) void attn_pass1()
{
    extern __shared__ uint32_t smu[];
    uint32_t* As    = smu;
    uint32_t* Bs[2] = { smu + P1_ASZ, smu + 2 * P1_ASZ };

    const int b  = blockIdx.y;
    const int m0 = blockIdx.x * 128;
    const int tid = threadIdx.x;
    const int lane = tid & 31, w = tid >> 5;
    const int gid = lane >> 2, tig = lane & 3;
    const int wm = w * 16;
    const int R0 = m0 + wm + gid;

    const uint32_t sbase = smem_u32(smu);
    const uint32_t aoff = ((wm + (lane & 15)) * P1_PITCH + ((lane & 16) ? 4 : 0)) * 4;
    const uint32_t boff = (((lane & 7) + ((lane & 16) >> 1)) * P1_PITCH + ((lane & 8) ? 4 : 0)) * 4;

    #pragma unroll
    for (int l = 0; l < 16; l++) {
        int i = tid + l * 256;
        int r = i >> 5, c = i & 31;
        CP_A16(smem_u32(As + r * P1_PITCH + c * 4),
               g_qh + ((size_t)b * NN + m0 + r) * CQ + c * 8);
    }
    #pragma unroll
    for (int l = 0; l < 16; l++) {
        int i = tid + l * 256;
        int r = i >> 5, c = i & 31;
        CP_A16(smem_u32(Bs[0] + r * P1_PITCH + c * 4),
               g_kh + ((size_t)b * NN + r) * CQ + c * 8);
    }
    CP_COMMIT();
    CP_WAIT0();
    __syncthreads();

    float run_m0 = -INFINITY, run_m1 = -INFINITY, run_s0 = 0.f, run_s1 = 0.f;

    for (int s = 0; s < 32; s++) {
        const int cur = s & 1, nxt = cur ^ 1;
        if (s + 1 < 32) {
            const __nv_bfloat16* src = g_kh + ((size_t)b * NN + (s + 1) * 128) * CQ;
            #pragma unroll
            for (int l = 0; l < 16; l++) {
                int i = tid + l * 256;
                int r = i >> 5, c = i & 31;
                CP_A16(smem_u32(Bs[nxt] + r * P1_PITCH + c * 4), src + (size_t)r * CQ + c * 8);
            }
        }
        CP_COMMIT();

        float acc[16][4];
        #pragma unroll
        for (int t = 0; t < 16; t++)
            #pragma unroll
            for (int j = 0; j < 4; j++) acc[t][j] = 0.f;

        const uint32_t abase = sbase + aoff;
        const uint32_t bbase = sbase + (uint32_t)((1 + cur) * P1_ASZ) * 4 + boff;
        #pragma unroll
        for (int ks = 0; ks < 16; ks++) {
            uint32_t a[4];
            ldm_x4(a, abase + ks * 32);
            #pragma unroll
            for (int j = 0; j < 8; j++) {
                uint32_t bf[4];
                ldm_x4(bf, bbase + (uint32_t)(j * 16 * P1_PITCH) * 4 + ks * 32);
                mma_bf16(acc[2 * j],     a[0], a[1], a[2], a[3], bf[0], bf[1]);
                mma_bf16(acc[2 * j + 1], a[0], a[1], a[2], a[3], bf[2], bf[3]);
            }
        }

        float vm0 = -INFINITY, vm1 = -INFINITY;
        #pragma unroll
        for (int t = 0; t < 16; t++) {
            vm0 = fmaxf(vm0, fmaxf(acc[t][0], acc[t][1]));
            vm1 = fmaxf(vm1, fmaxf(acc[t][2], acc[t][3]));
        }
        vm0 = fmaxf(vm0, __shfl_xor_sync(0xffffffffu, vm0, 1));
        vm0 = fmaxf(vm0, __shfl_xor_sync(0xffffffffu, vm0, 2));
        vm1 = fmaxf(vm1, __shfl_xor_sync(0xffffffffu, vm1, 1));
        vm1 = fmaxf(vm1, __shfl_xor_sync(0xffffffffu, vm1, 2));
        float nm0 = fmaxf(run_m0, vm0);
        float nm1 = fmaxf(run_m1, vm1);
        float s0 = 0.f, s1 = 0.f;
        #pragma unroll
        for (int t = 0; t < 16; t++) {
            s0 += __expf(acc[t][0] - nm0) + __expf(acc[t][1] - nm0);
            s1 += __expf(acc[t][2] - nm1) + __expf(acc[t][3] - nm1);
        }
        s0 += __shfl_xor_sync(0xffffffffu, s0, 1);
        s0 += __shfl_xor_sync(0xffffffffu, s0, 2);
        s1 += __shfl_xor_sync(0xffffffffu, s1, 1);
        s1 += __shfl_xor_sync(0xffffffffu, s1, 2);
        run_s0 = run_s0 * __expf(run_m0 - nm0) + s0;
        run_s1 = run_s1 * __expf(run_m1 - nm1) + s1;
        run_m0 = nm0;
        run_m1 = nm1;

        __nv_bfloat16* so0 = g_Sh + ((size_t)b * NN + R0) * NN + s * 128;
        __nv_bfloat16* so1 = so0 + (size_t)8 * NN;
        #pragma unroll
        for (int t = 0; t < 16; t++) {
            int col = t * 8 + tig * 2;
            *reinterpret_cast<__nv_bfloat162*>(so0 + col) = __floats2bfloat162_rn(acc[t][0], acc[t][1]);
            *reinterpret_cast<__nv_bfloat162*>(so1 + col) = __floats2bfloat162_rn(acc[t][2], acc[t][3]);
        }

        CP_WAIT0();
        __syncthreads();
    }

    if (tig == 0) {
        g_rowmax[b * NN + R0]     = run_m0;
        g_rowsum[b * NN + R0]     = run_s0;
        g_rowmax[b * NN + R0 + 8] = run_m1;
        g_rowsum[b * NN + R0 + 8] = run_s1;
    }
}

// ============================================================
// Attention pass 2: stream bf16 S, per-slice column sums.
// ============================================================
__global__ __launch_bounds__(256) void attn_pass2()
{
    __shared__ float rm[128], rz[128];
    const int b  = blockIdx.z;
    const int ms = blockIdx.y;
    const int nb = blockIdx.x * 2048;
    const int tid = threadIdx.x;

    if (tid < 128) {
        rm[tid] = g_rowmax[b * NN + ms * 128 + tid];
        rz[tid] = 1.0f / g_rowsum[b * NN + ms * 128 + tid];
    }
    __syncthreads();

    const __nv_bfloat16* Sp = g_Sh + ((size_t)b * NN + ms * 128) * NN + nb + tid * 8;
    float a[8];
    #pragma unroll
    for (int i = 0; i < 8; i++) a[i] = 0.f;

    for (int m = 0; m < 128; m++) {
        uint4 r = *reinterpret_cast<const uint4*>(Sp + (size_t)m * NN);
        float mx = rm[m], z = rz[m];
        __nv_bfloat162 p0 = *reinterpret_cast<__nv_bfloat162*>(&r.x);
        __nv_bfloat162 p1 = *reinterpret_cast<__nv_bfloat162*>(&r.y);
        __nv_bfloat162 p2 = *reinterpret_cast<__nv_bfloat162*>(&r.z);
        __nv_bfloat162 p3 = *reinterpret_cast<__nv_bfloat162*>(&r.w);
        a[0] += __expf(__bfloat162float(p0.x) - mx) * z;
        a[1] += __expf(__bfloat162float(p0.y) - mx) * z;
        a[2] += __expf(__bfloat162float(p1.x) - mx) * z;
        a[3] += __expf(__bfloat162float(p1.y) - mx) * z;
        a[4] += __expf(__bfloat162float(p2.x) - mx) * z;
        a[5] += __expf(__bfloat162float(p2.y) - mx) * z;
        a[6] += __expf(__bfloat162float(p3.x) - mx) * z;
        a[7] += __expf(__bfloat162float(p3.y) - mx) * z;
    }
    const float sc = 1.0f / NN;
    float* wp = g_wpart + (size_t)ms * (BB * NN) + b * NN + nb + tid * 8;
    *reinterpret_cast<float4*>(wp)     = make_float4(a[0] * sc, a[1] * sc, a[2] * sc, a[3] * sc);
    *reinterpret_cast<float4*>(wp + 4) = make_float4(a[4] * sc, a[5] * sc, a[6] * sc, a[7] * sc);
}

__global__ void reduce_w_kernel()
{
    const int flat = blockIdx.x * 256 + threadIdx.x;
    float s = 0.f;
    #pragma unroll
    for (int ms = 0; ms < 32; ms++) s += g_wpart[ms * (BB * NN) + flat];
    g_w[flat] = s;
}

// ============================================================
// Weighted/plain reductions over spatial axis
// ============================================================
__global__ void reduce_xw_kernel(const float* __restrict__ img,
                                 const float* __restrict__ pc2d)
{
    const int b = blockIdx.y;
    const int c = blockIdx.x;
    const int t = threadIdx.x;
    const float* wv = g_w + b * NN;
    __shared__ float s1s[4], s2s[4];

    float s1 = 0.f, s2 = 0.f;
    if (c < CQ) {
        const float* row = img + ((size_t)b * CQ + c) * NN;
        for (int n = t; n < NN; n += 128) { float x = row[n]; s1 += x * wv[n]; s2 += x; }
    } else {
        const float* row = pc2d + ((size_t)b * CK + (c - CQ)) * NN;
        for (int n = t; n < NN; n += 128) s1 += row[n] * wv[n];
    }
    #pragma unroll
    for (int o = 16; o; o >>= 1) {
        s1 += __shfl_xor_sync(0xffffffffu, s1, o);
        s2 += __shfl_xor_sync(0xffffffffu, s2, o);
    }
    if ((t & 31) == 0) { s1s[t >> 5] = s1; s2s[t >> 5] = s2; }
    __syncthreads();
    if (t == 0) {
        float a = s1s[0] + s1s[1] + s1s[2] + s1s[3];
        float m = s2s[0] + s2s[1] + s2s[2] + s2s[3];
        if (c < CQ) {
            g_ximg[b * CQ + c] = a;
            g_imgmean[b * CQ + c] = m * (1.0f / NN);
        } else {
            g_xpc[b * CK + (c - CQ)] = a;
        }
    }
}

// ============================================================
// Fused vector
// ============================================================
__global__ void fuse_kernel(const float* __restrict__ Wvi, const float* __restrict__ bvi,
                            const float* __restrict__ Wvp, const float* __restrict__ bvp,
                            const float* __restrict__ gamma1)
{
    const int b = blockIdx.y;
    const int chunk = blockIdx.x;
    const int t = threadIdx.x;
    __shared__ float xs[2048];

    if (chunk == 0) {
        if (t < CQ) xs[t] = g_ximg[b * CQ + t];
        __syncthreads();
        float acc = 0.f;
        const float* wr = Wvi + (size_t)t * CQ;
        for (int i = 0; i < CQ; i++) acc += wr[i] * xs[i];
        float g = gamma1[0];
        g_fused[b * (CQ + CK) + t] = g * (acc + bvi[t]) + g_imgmean[b * CQ + t];
    } else {
        for (int i = t; i < CK; i += 256) xs[i] = g_xpc[b * CK + i];
        __syncthreads();
        int c2 = (chunk - 1) * 256 + t;
        float acc = 0.f;
        const float* wr = Wvp + (size_t)c2 * CK;
        for (int i = 0; i < CK; i++) acc += wr[i] * xs[i];
        g_fused[b * (CQ + CK) + CQ + c2] = acc + bvp[c2];
    }
}

// ============================================================
// MLP head + log_softmax
// ============================================================
__device__ __forceinline__ float warp_red(float v)
{
    #pragma unroll
    for (int o = 16; o; o >>= 1) v += __shfl_xor_sync(0xffffffffu, v, o);
    return v;
}

__global__ void head_kernel(const float* __restrict__ W1, const float* __restrict__ b1,
                            const float* __restrict__ W2, const float* __restrict__ b2,
                            float* __restrict__ out)
{
    const int b = blockIdx.x;
    __shared__ float fs[CQ + CK];
    __shared__ float hs[1024];
    __shared__ float lg[NCLS];
    __shared__ float mxs, lses;
    const int tid = threadIdx.x;
    const int warp = tid >> 5, lane = tid & 31;

    for (int i = tid; i < CQ + CK; i += 256) fs[i] = g_fused[b * (CQ + CK) + i];
    __syncthreads();

    for (int j = warp; j < 1024; j += 8) {
        const float* wr = W1 + (size_t)j * (CQ + CK);
        float s = 0.f;
        for (int i = lane; i < CQ + CK; i += 32) s += fs[i] * wr[i];
        s = warp_red(s);
        if (lane == 0) hs[j] = fmaxf(s + b1[j], 0.f);
    }
    __syncthreads();

    for (int k = warp; k < NCLS; k += 8) {
        const float* wr = W2 + (size_t)k * 1024;
        float s = 0.f;
        for (int i = lane; i < 1024; i += 32) s += hs[i] * wr[i];
        s = warp_red(s);
        if (lane == 0) lg[k] = s + b2[k];
    }
    __syncthreads();

    if (tid == 0) {
        float m = -INFINITY;
        for (int k = 0; k < NCLS; k++) m = fmaxf(m, lg[k]);
        float s = 0.f;
        for (int k = 0; k < NCLS; k++) s += expf(lg[k] - m);
        mxs = m; lses = logf(s);
    }
    __syncthreads();
    if (tid < NCLS) out[b * NCLS + tid] = lg[tid] - mxs - lses;
}

// ============================================================
extern "C" void kernel_launch(void* const* d_in, const int* in_sizes, int n_in,
                              void* d_out, int out_size)
{
    const float* img    = (const float*)d_in[0];
    const float* pc2d   = (const float*)d_in[1];
    const float* Wq     = (const float*)d_in[2];
    const float* bq     = (const float*)d_in[3];
    const float* Wk     = (const float*)d_in[4];
    const float* bk     = (const float*)d_in[5];
    const float* Wvi    = (const float*)d_in[6];
    const float* bvi    = (const float*)d_in[7];
    const float* Wvp    = (const float*)d_in[8];
    const float* bvp    = (const float*)d_in[9];
    const float* gamma1 = (const float*)d_in[10];
    const float* W1     = (const float*)d_in[11];
    const float* b1     = (const float*)d_in[12];
    const float* W2     = (const float*)d_in[13];
    const float* b2     = (const float*)d_in[14];
    float* out = (float*)d_out;

    cudaFuncSetAttribute(proj_kernel<CQ, 0>, cudaFuncAttributeMaxDynamicSharedMemorySize, PROJ_SMEM);
    cudaFuncSetAttribute(proj_kernel<CK, 1>, cudaFuncAttributeMaxDynamicSharedMemorySize, PROJ_SMEM);
    cudaFuncSetAttribute(attn_pass1, cudaFuncAttributeMaxDynamicSharedMemorySize, P1_SMEM);

    __nv_bfloat16* d_imgh = nullptr; cudaGetSymbolAddress((void**)&d_imgh, g_imgh);
    __nv_bfloat16* d_pch  = nullptr; cudaGetSymbolAddress((void**)&d_pch,  g_pch);
    __nv_bfloat16* d_wqh  = nullptr; cudaGetSymbolAddress((void**)&d_wqh,  g_wqh);
    __nv_bfloat16* d_wkh  = nullptr; cudaGetSymbolAddress((void**)&d_wkh,  g_wkh);

    dim3 blk(256);
    // ordered so that absolute launch index 5 (= our index 3) is proj_k
    cvt_x_kernel<CK><<<dim3(NN / 32, CK / 32, BB), dim3(32, 8)>>>(pc2d, d_pch);      // 0
    cvt_wqk_kernel<<<256, blk>>>(Wq, Wk);                                            // 1
    cvt_x_kernel<CQ><<<dim3(NN / 32, CQ / 32, BB), dim3(32, 8)>>>(img, d_imgh);      // 2
    proj_kernel<CK, 1><<<dim3(NN / 128, CQ / 128, BB), blk, PROJ_SMEM>>>(d_wkh, d_pch, bk);  // 3 <- profiled
    proj_kernel<CQ, 0><<<dim3(NN / 128, CQ / 128, BB), blk, PROJ_SMEM>>>(d_wqh, d_imgh, bq); // 4
    attn_pass1<<<dim3(NN / 128, BB), blk, P1_SMEM>>>();                              // 5
    attn_pass2<<<dim3(2, 32, BB), blk>>>();                                          // 6
    reduce_w_kernel<<<dim3(BB * NN / 256), blk>>>();                                 // 7
    reduce_xw_kernel<<<dim3(CQ + CK, BB), dim3(128)>>>(img, pc2d);                   // 8
    fuse_kernel<<<dim3(1 + CK / 256, BB), blk>>>(Wvi, bvi, Wvp, bvp, gamma1);        // 9
    head_kernel<<<dim3(BB), blk>>>(W1, b1, W2, b2, out);                             // 10
}

// round 8
// speedup vs baseline: 9.1983x; 1.0511x over previous
#include <cuda_runtime.h>
#include <cuda_bf16.h>
#include <math.h>
#include <stdint.h>

#define BB 16
#define CQ 256
#define CK 2048
#define NN 4096
#define NCLS 40

// ---- scratch (static __device__ arrays; no allocation) ----
__device__ __nv_bfloat16 g_imgh[(size_t)BB * NN * CQ];  // img  [b][n][c] bf16
__device__ __nv_bfloat16 g_pch[(size_t)BB * NN * CK];   // pc2d [b][n][c] bf16
__device__ __nv_bfloat16 g_wqh[CQ * CQ];
__device__ __nv_bfloat16 g_wkh[CQ * CK];
__device__ __nv_bfloat16 g_qh[(size_t)BB * NN * CQ];    // q [b][n][c] bf16
__device__ __nv_bfloat16 g_kh[(size_t)BB * NN * CQ];    // k [b][n][c] bf16
__device__ __nv_bfloat16 g_Sh[(size_t)BB * NN * NN];    // S [b][m][n] bf16
__device__ float g_rowmax[BB * NN];
__device__ float g_rowsum[BB * NN];
__device__ float g_wpart[32 * BB * NN];
__device__ float g_w[BB * NN];
__device__ float g_ximg[BB * CQ];
__device__ float g_imgmean[BB * CQ];
__device__ float g_xpc[BB * CK];
__device__ float g_fused[BB * (CQ + CK)];

// ============================================================
// helpers
// ============================================================
__device__ __forceinline__ uint32_t smem_u32(const void* p) {
    uint32_t a;
    asm("{ .reg .u64 t; cvta.to.shared.u64 t, %1; cvt.u32.u64 %0, t; }" : "=r"(a) : "l"(p));
    return a;
}
__device__ __forceinline__ void mma_bf16(float* c, uint32_t a0, uint32_t a1, uint32_t a2, uint32_t a3,
                                         uint32_t b0, uint32_t b1)
{
    asm volatile(
        "mma.sync.aligned.m16n8k16.row.col.f32.bf16.bf16.f32 "
        "{%0,%1,%2,%3},{%4,%5,%6,%7},{%8,%9},{%0,%1,%2,%3};"
        : "+f"(c[0]), "+f"(c[1]), "+f"(c[2]), "+f"(c[3])
        : "r"(a0), "r"(a1), "r"(a2), "r"(a3), "r"(b0), "r"(b1));
}
__device__ __forceinline__ void ldm_x4(uint32_t* r, uint32_t addr)
{
    asm volatile("ldmatrix.sync.aligned.m8n8.x4.shared.b16 {%0,%1,%2,%3}, [%4];"
        : "=r"(r[0]), "=r"(r[1]), "=r"(r[2]), "=r"(r[3]) : "r"(addr));
}
#define CP_A16(dst, src) \
    asm volatile("cp.async.ca.shared.global [%0], [%1], 16;" :: "r"(dst), "l"(src))
#define CP_COMMIT() asm volatile("cp.async.commit_group;" ::: "memory")
#define CP_WAIT0()  asm volatile("cp.async.wait_group 0;" ::: "memory")

// ============================================================
// Transpose-convert: in[b][C][NN] fp32 -> out[b][NN][C] bf16
// ============================================================
template <int C>
__global__ __launch_bounds__(256) void cvt_x_kernel(const float* __restrict__ in,
                                                    __nv_bfloat16* __restrict__ out)
{
    __shared__ float t[32][33];
    const int b  = blockIdx.z;
    const int c0 = blockIdx.y * 32;
    const int n0 = blockIdx.x * 32;
    const int tx = threadIdx.x, ty = threadIdx.y;

    const float* ib = in + ((size_t)b * C + c0) * NN + n0;
    #pragma unroll
    for (int i = 0; i < 4; i++) {
        int c = ty + i * 8;
        t[c][tx] = ib[(size_t)c * NN + tx];
    }
    __syncthreads();
    __nv_bfloat16* ob = out + ((size_t)b * NN + n0) * C + c0;
    #pragma unroll
    for (int i = 0; i < 4; i++) {
        int r = ty + i * 8;
        ob[(size_t)r * C + tx] = __float2bfloat16_rn(t[tx][r]);
    }
}

__global__ void cvt_wqk_kernel(const float* __restrict__ Wq, const float* __restrict__ Wk)
{
    const int total = CQ * CQ + CQ * CK;
    int i = blockIdx.x * 256 + threadIdx.x;
    for (; i < total; i += gridDim.x * 256) {
        if (i < CQ * CQ) g_wqh[i] = __float2bfloat16_rn(Wq[i]);
        else             g_wkh[i - CQ * CQ] = __float2bfloat16_rn(Wk[i - CQ * CQ]);
    }
}

// ============================================================
// Projection GEMM (bf16 mma + ldmatrix, 512 thr):
// out[b][n][m] = W[m,:]·Xh[b][n,:]+bias ; block 128m x 128n; K-chunk 128.
// 16 warps: warp = (wq m-strip of 16) x (wh n-half of 64).
// ============================================================
#define PJ_PITCH 68
#define PJ_TSZ   (128 * PJ_PITCH)
#define PROJ_SMEM (4 * PJ_TSZ * 4)

template <int KDIM, int WHICH>
__global__ __launch_bounds__(512) void proj_kernel(const __nv_bfloat16* __restrict__ Wh,
                                                   const __nv_bfloat16* __restrict__ Xh,
                                                   const float* __restrict__ bias)
{
    extern __shared__ uint32_t smu[];
    const int b  = blockIdx.z;
    const int m0 = blockIdx.y * 128;
    const int n0 = blockIdx.x * 128;
    const int tid = threadIdx.x;
    const int lane = tid & 31, w = tid >> 5;
    const int wq = w & 7, wh = w >> 3;
    const int gid = lane >> 2, tig = lane & 3;
    const int NCH = KDIM / 128;
    const __nv_bfloat16* Xb = Xh + (size_t)b * NN * KDIM + (size_t)n0 * KDIM;

    const uint32_t sbase = smem_u32(smu);
    const uint32_t aoff = ((wq * 16 + (lane & 15)) * PJ_PITCH + ((lane & 16) ? 4 : 0)) * 4;
    const uint32_t boff = ((wh * 64 + (lane & 7) + ((lane & 16) >> 1)) * PJ_PITCH + ((lane & 8) ? 4 : 0)) * 4;

    float acc[8][4];
    #pragma unroll
    for (int t = 0; t < 8; t++)
        #pragma unroll
        for (int j = 0; j < 4; j++) acc[t][j] = 0.f;

    #pragma unroll
    for (int l = 0; l < 4; l++) {
        int i = tid + l * 512;
        int r = i >> 4, c = i & 15;
        CP_A16(smem_u32(smu + r * PJ_PITCH + c * 4), Wh + (size_t)(m0 + r) * KDIM + c * 8);
    }
    #pragma unroll
    for (int l = 0; l < 4; l++) {
        int i = tid + l * 512;
        int r = i >> 4, c = i & 15;
        CP_A16(smem_u32(smu + 2 * PJ_TSZ + r * PJ_PITCH + c * 4), Xb + (size_t)r * KDIM + c * 8);
    }
    CP_COMMIT();
    CP_WAIT0();
    __syncthreads();

    for (int kc = 0; kc < NCH; kc++) {
        const int cur = kc & 1, nxt = cur ^ 1;
        if (kc + 1 < NCH) {
            const int kb = (kc + 1) * 128;
            #pragma unroll
            for (int l = 0; l < 4; l++) {
                int i = tid + l * 512;
                int r = i >> 4, c = i & 15;
                CP_A16(smem_u32(smu + nxt * PJ_TSZ + r * PJ_PITCH + c * 4),
                       Wh + (size_t)(m0 + r) * KDIM + kb + c * 8);
            }
            #pragma unroll
            for (int l = 0; l < 4; l++) {
                int i = tid + l * 512;
                int r = i >> 4, c = i & 15;
                CP_A16(smem_u32(smu + (2 + nxt) * PJ_TSZ + r * PJ_PITCH + c * 4),
                       Xb + (size_t)r * KDIM + kb + c * 8);
            }
        }
        CP_COMMIT();

        const uint32_t abase = sbase + (uint32_t)(cur * PJ_TSZ) * 4 + aoff;
        const uint32_t bbase = sbase + (uint32_t)((2 + cur) * PJ_TSZ) * 4 + boff;
        #pragma unroll
        for (int ks = 0; ks < 8; ks++) {
            uint32_t a[4];
            ldm_x4(a, abase + ks * 32);
            #pragma unroll
            for (int j = 0; j < 4; j++) {
                uint32_t bf[4];
                ldm_x4(bf, bbase + (uint32_t)(j * 16 * PJ_PITCH) * 4 + ks * 32);
                mma_bf16(acc[2 * j],     a[0], a[1], a[2], a[3], bf[0], bf[1]);
                mma_bf16(acc[2 * j + 1], a[0], a[1], a[2], a[3], bf[2], bf[3]);
            }
        }
        CP_WAIT0();
        __syncthreads();
    }

    __nv_bfloat16* out = (WHICH == 0) ? g_qh : g_kh;
    const int R0 = m0 + wq * 16 + gid;
    const float bv0 = bias[R0], bv1 = bias[R0 + 8];
    #pragma unroll
    for (int t = 0; t < 8; t++) {
        int n = n0 + wh * 64 + t * 8 + tig * 2;
        __nv_bfloat16* p0 = out + ((size_t)b * NN + n) * CQ;
        __nv_bfloat16* p1 = p0 + CQ;
        p0[R0]     = __float2bfloat16_rn(acc[t][0] + bv0);
        p1[R0]     = __float2bfloat16_rn(acc[t][1] + bv0);
        p0[R0 + 8] = __float2bfloat16_rn(acc[t][2] + bv1);
        p1[R0 + 8] = __float2bfloat16_rn(acc[t][3] + bv1);
    }
}

// ============================================================
// Attention pass 1 (bf16 mma + ldmatrix, 512 thr): per (b, 128 m-tile)
// sweep all n. 16 warps = 8 m-strips x 2 n-halves; per-half online
// (max,sum) merged once at the end via smem.
// ============================================================
#define P1_PITCH 132
#define P1_ASZ   (128 * P1_PITCH)
#define P1_SMEM  ((3 * P1_ASZ + 512) * 4)

__global__ __launch_bounds__(512) void attn_pass1()
{
    extern __shared__ uint32_t smu[];
    float* smM = reinterpret_cast<float*>(smu + 3 * P1_ASZ);        // [2][128]
    float* smS = smM + 256;

    const int b  = blockIdx.y;
    const int m0 = blockIdx.x * 128;
    const int tid = threadIdx.x;
    const int lane = tid & 31, w = tid >> 5;
    const int wq = w & 7, wh = w >> 3;
    const int gid = lane >> 2, tig = lane & 3;
    const int R0 = m0 + wq * 16 + gid;

    const uint32_t sbase = smem_u32(smu);
    const uint32_t aoff = ((wq * 16 + (lane & 15)) * P1_PITCH + ((lane & 16) ? 4 : 0)) * 4;
    const uint32_t boff = ((wh * 64 + (lane & 7) + ((lane & 16) >> 1)) * P1_PITCH + ((lane & 8) ? 4 : 0)) * 4;

    #pragma unroll
    for (int l = 0; l < 8; l++) {
        int i = tid + l * 512;
        int r = i >> 5, c = i & 31;
        CP_A16(smem_u32(smu + r * P1_PITCH + c * 4),
               g_qh + ((size_t)b * NN + m0 + r) * CQ + c * 8);
    }
    #pragma unroll
    for (int l = 0; l < 8; l++) {
        int i = tid + l * 512;
        int r = i >> 5, c = i & 31;
        CP_A16(smem_u32(smu + P1_ASZ + r * P1_PITCH + c * 4),
               g_kh + ((size_t)b * NN + r) * CQ + c * 8);
    }
    CP_COMMIT();
    CP_WAIT0();
    __syncthreads();

    float run_m0 = -INFINITY, run_m1 = -INFINITY, run_s0 = 0.f, run_s1 = 0.f;

    for (int s = 0; s < 32; s++) {
        const int cur = s & 1, nxt = cur ^ 1;
        if (s + 1 < 32) {
            const __nv_bfloat16* src = g_kh + ((size_t)b * NN + (s + 1) * 128) * CQ;
            #pragma unroll
            for (int l = 0; l < 8; l++) {
                int i = tid + l * 512;
                int r = i >> 5, c = i & 31;
                CP_A16(smem_u32(smu + (1 + nxt) * P1_ASZ + r * P1_PITCH + c * 4),
                       src + (size_t)r * CQ + c * 8);
            }
        }
        CP_COMMIT();

        float acc[8][4];
        #pragma unroll
        for (int t = 0; t < 8; t++)
            #pragma unroll
            for (int j = 0; j < 4; j++) acc[t][j] = 0.f;

        const uint32_t abase = sbase + aoff;
        const uint32_t bbase = sbase + (uint32_t)((1 + cur) * P1_ASZ) * 4 + boff;
        #pragma unroll
        for (int ks = 0; ks < 16; ks++) {
            uint32_t a[4];
            ldm_x4(a, abase + ks * 32);
            #pragma unroll
            for (int j = 0; j < 4; j++) {
                uint32_t bf[4];
                ldm_x4(bf, bbase + (uint32_t)(j * 16 * P1_PITCH) * 4 + ks * 32);
                mma_bf16(acc[2 * j],     a[0], a[1], a[2], a[3], bf[0], bf[1]);
                mma_bf16(acc[2 * j + 1], a[0], a[1], a[2], a[3], bf[2], bf[3]);
            }
        }

        float vm0 = -INFINITY, vm1 = -INFINITY;
        #pragma unroll
        for (int t = 0; t < 8; t++) {
            vm0 = fmaxf(vm0, fmaxf(acc[t][0], acc[t][1]));
            vm1 = fmaxf(vm1, fmaxf(acc[t][2], acc[t][3]));
        }
        vm0 = fmaxf(vm0, __shfl_xor_sync(0xffffffffu, vm0, 1));
        vm0 = fmaxf(vm0, __shfl_xor_sync(0xffffffffu, vm0, 2));
        vm1 = fmaxf(vm1, __shfl_xor_sync(0xffffffffu, vm1, 1));
        vm1 = fmaxf(vm1, __shfl_xor_sync(0xffffffffu, vm1, 2));
        float nm0 = fmaxf(run_m0, vm0);
        float nm1 = fmaxf(run_m1, vm1);
        float s0 = 0.f, s1 = 0.f;
        #pragma unroll
        for (int t = 0; t < 8; t++) {
            s0 += __expf(acc[t][0] - nm0) + __expf(acc[t][1] - nm0);
            s1 += __expf(acc[t][2] - nm1) + __expf(acc[t][3] - nm1);
        }
        s0 += __shfl_xor_sync(0xffffffffu, s0, 1);
        s0 += __shfl_xor_sync(0xffffffffu, s0, 2);
        s1 += __shfl_xor_sync(0xffffffffu, s1, 1);
        s1 += __shfl_xor_sync(0xffffffffu, s1, 2);
        run_s0 = run_s0 * __expf(run_m0 - nm0) + s0;
        run_s1 = run_s1 * __expf(run_m1 - nm1) + s1;
        run_m0 = nm0;
        run_m1 = nm1;

        __nv_bfloat16* so0 = g_Sh + ((size_t)b * NN + R0) * NN + s * 128 + wh * 64;
        __nv_bfloat16* so1 = so0 + (size_t)8 * NN;
        #pragma unroll
        for (int t = 0; t < 8; t++) {
            int col = t * 8 + tig * 2;
            *reinterpret_cast<__nv_bfloat162*>(so0 + col) = __floats2bfloat162_rn(acc[t][0], acc[t][1]);
            *reinterpret_cast<__nv_bfloat162*>(so1 + col) = __floats2bfloat162_rn(acc[t][2], acc[t][3]);
        }

        CP_WAIT0();
        __syncthreads();
    }

    // merge the two n-halves' stats per row
    if (tig == 0) {
        int r = wq * 16 + gid;
        smM[wh * 128 + r]     = run_m0;
        smS[wh * 128 + r]     = run_s0;
        smM[wh * 128 + r + 8] = run_m1;
        smS[wh * 128 + r + 8] = run_s1;
    }
    __syncthreads();
    if (tid < 128) {
        float ma = smM[tid], mb = smM[128 + tid];
        float sa = smS[tid], sb = smS[128 + tid];
        float nm = fmaxf(ma, mb);
        g_rowmax[b * NN + m0 + tid] = nm;
        g_rowsum[b * NN + m0 + tid] = sa * __expf(ma - nm) + sb * __expf(mb - nm);
    }
}

// ============================================================
// Attention pass 2: stream bf16 S, per-slice column sums.
// ============================================================
__global__ __launch_bounds__(256) void attn_pass2()
{
    __shared__ float rm[128], rz[128];
    const int b  = blockIdx.z;
    const int ms = blockIdx.y;
    const int nb = blockIdx.x * 2048;
    const int tid = threadIdx.x;

    if (tid < 128) {
        rm[tid] = g_rowmax[b * NN + ms * 128 + tid];
        rz[tid] = 1.0f / g_rowsum[b * NN + ms * 128 + tid];
    }
    __syncthreads();

    const __nv_bfloat16* Sp = g_Sh + ((size_t)b * NN + ms * 128) * NN + nb + tid * 8;
    float a[8];
    #pragma unroll
    for (int i = 0; i < 8; i++) a[i] = 0.f;

    for (int m = 0; m < 128; m++) {
        uint4 r = *reinterpret_cast<const uint4*>(Sp + (size_t)m * NN);
        float mx = rm[m], z = rz[m];
        __nv_bfloat162 p0 = *reinterpret_cast<__nv_bfloat162*>(&r.x);
        __nv_bfloat162 p1 = *reinterpret_cast<__nv_bfloat162*>(&r.y);
        __nv_bfloat162 p2 = *reinterpret_cast<__nv_bfloat162*>(&r.z);
        __nv_bfloat162 p3 = *reinterpret_cast<__nv_bfloat162*>(&r.w);
        a[0] += __expf(__bfloat162float(p0.x) - mx) * z;
        a[1] += __expf(__bfloat162float(p0.y) - mx) * z;
        a[2] += __expf(__bfloat162float(p1.x) - mx) * z;
        a[3] += __expf(__bfloat162float(p1.y) - mx) * z;
        a[4] += __expf(__bfloat162float(p2.x) - mx) * z;
        a[5] += __expf(__bfloat162float(p2.y) - mx) * z;
        a[6] += __expf(__bfloat162float(p3.x) - mx) * z;
        a[7] += __expf(__bfloat162float(p3.y) - mx) * z;
    }
    const float sc = 1.0f / NN;
    float* wp = g_wpart + (size_t)ms * (BB * NN) + b * NN + nb + tid * 8;
    *reinterpret_cast<float4*>(wp)     = make_float4(a[0] * sc, a[1] * sc, a[2] * sc, a[3] * sc);
    *reinterpret_cast<float4*>(wp + 4) = make_float4(a[4] * sc, a[5] * sc, a[6] * sc, a[7] * sc);
}

__global__ void reduce_w_kernel()
{
    const int flat = blockIdx.x * 256 + threadIdx.x;
    float s = 0.f;
    #pragma unroll
    for (int ms = 0; ms < 32; ms++) s += g_wpart[ms * (BB * NN) + flat];
    g_w[flat] = s;
}

// ============================================================
// Weighted/plain reductions over spatial axis
// ============================================================
__global__ void reduce_xw_kernel(const float* __restrict__ img,
                                 const float* __restrict__ pc2d)
{
    const int b = blockIdx.y;
    const int c = blockIdx.x;
    const int t = threadIdx.x;
    const float* wv = g_w + b * NN;
    __shared__ float s1s[4], s2s[4];

    float s1 = 0.f, s2 = 0.f;
    if (c < CQ) {
        const float* row = img + ((size_t)b * CQ + c) * NN;
        for (int n = t; n < NN; n += 128) { float x = row[n]; s1 += x * wv[n]; s2 += x; }
    } else {
        const float* row = pc2d + ((size_t)b * CK + (c - CQ)) * NN;
        for (int n = t; n < NN; n += 128) s1 += row[n] * wv[n];
    }
    #pragma unroll
    for (int o = 16; o; o >>= 1) {
        s1 += __shfl_xor_sync(0xffffffffu, s1, o);
        s2 += __shfl_xor_sync(0xffffffffu, s2, o);
    }
    if ((t & 31) == 0) { s1s[t >> 5] = s1; s2s[t >> 5] = s2; }
    __syncthreads();
    if (t == 0) {
        float a = s1s[0] + s1s[1] + s1s[2] + s1s[3];
        float m = s2s[0] + s2s[1] + s2s[2] + s2s[3];
        if (c < CQ) {
            g_ximg[b * CQ + c] = a;
            g_imgmean[b * CQ + c] = m * (1.0f / NN);
        } else {
            g_xpc[b * CK + (c - CQ)] = a;
        }
    }
}

// ============================================================
// Fused vector
// ============================================================
__global__ void fuse_kernel(const float* __restrict__ Wvi, const float* __restrict__ bvi,
                            const float* __restrict__ Wvp, const float* __restrict__ bvp,
                            const float* __restrict__ gamma1)
{
    const int b = blockIdx.y;
    const int chunk = blockIdx.x;
    const int t = threadIdx.x;
    __shared__ float xs[2048];

    if (chunk == 0) {
        if (t < CQ) xs[t] = g_ximg[b * CQ + t];
        __syncthreads();
        float acc = 0.f;
        const float* wr = Wvi + (size_t)t * CQ;
        for (int i = 0; i < CQ; i++) acc += wr[i] * xs[i];
        float g = gamma1[0];
        g_fused[b * (CQ + CK) + t] = g * (acc + bvi[t]) + g_imgmean[b * CQ + t];
    } else {
        for (int i = t; i < CK; i += 256) xs[i] = g_xpc[b * CK + i];
        __syncthreads();
        int c2 = (chunk - 1) * 256 + t;
        float acc = 0.f;
        const float* wr = Wvp + (size_t)c2 * CK;
        for (int i = 0; i < CK; i++) acc += wr[i] * xs[i];
        g_fused[b * (CQ + CK) + CQ + c2] = acc + bvp[c2];
    }
}

// ============================================================
// MLP head + log_softmax
// ============================================================
__device__ __forceinline__ float warp_red(float v)
{
    #pragma unroll
    for (int o = 16; o; o >>= 1) v += __shfl_xor_sync(0xffffffffu, v, o);
    return v;
}

__global__ void head_kernel(const float* __restrict__ W1, const float* __restrict__ b1,
                            const float* __restrict__ W2, const float* __restrict__ b2,
                            float* __restrict__ out)
{
    const int b = blockIdx.x;
    __shared__ float fs[CQ + CK];
    __shared__ float hs[1024];
    __shared__ float lg[NCLS];
    __shared__ float mxs, lses;
    const int tid = threadIdx.x;
    const int warp = tid >> 5, lane = tid & 31;

    for (int i = tid; i < CQ + CK; i += 256) fs[i] = g_fused[b * (CQ + CK) + i];
    __syncthreads();

    for (int j = warp; j < 1024; j += 8) {
        const float* wr = W1 + (size_t)j * (CQ + CK);
        float s = 0.f;
        for (int i = lane; i < CQ + CK; i += 32) s += fs[i] * wr[i];
        s = warp_red(s);
        if (lane == 0) hs[j] = fmaxf(s + b1[j], 0.f);
    }
    __syncthreads();

    for (int k = warp; k < NCLS; k += 8) {
        const float* wr = W2 + (size_t)k * 1024;
        float s = 0.f;
        for (int i = lane; i < 1024; i += 32) s += hs[i] * wr[i];
        s = warp_red(s);
        if (lane == 0) lg[k] = s + b2[k];
    }
    __syncthreads();

    if (tid == 0) {
        float m = -INFINITY;
        for (int k = 0; k < NCLS; k++) m = fmaxf(m, lg[k]);
        float s = 0.f;
        for (int k = 0; k < NCLS; k++) s += expf(lg[k] - m);
        mxs = m; lses = logf(s);
    }
    __syncthreads();
    if (tid < NCLS) out[b * NCLS + tid] = lg[tid] - mxs - lses;
}

// ============================================================
extern "C" void kernel_launch(void* const* d_in, const int* in_sizes, int n_in,
                              void* d_out, int out_size)
{
    const float* img    = (const float*)d_in[0];
    const float* pc2d   = (const float*)d_in[1];
    const float* Wq     = (const float*)d_in[2];
    const float* bq     = (const float*)d_in[3];
    const float* Wk     = (const float*)d_in[4];
    const float* bk     = (const float*)d_in[5];
    const float* Wvi    = (const float*)d_in[6];
    const float* bvi    = (const float*)d_in[7];
    const float* Wvp    = (const float*)d_in[8];
    const float* bvp    = (const float*)d_in[9];
    const float* gamma1 = (const float*)d_in[10];
    const float* W1     = (const float*)d_in[11];
    const float* b1     = (const float*)d_in[12];
    const float* W2     = (const float*)d_in[13];
    const float* b2     = (const float*)d_in[14];
    float* out = (float*)d_out;

    cudaFuncSetAttribute(proj_kernel<CQ, 0>, cudaFuncAttributeMaxDynamicSharedMemorySize, PROJ_SMEM);
    cudaFuncSetAttribute(proj_kernel<CK, 1>, cudaFuncAttributeMaxDynamicSharedMemorySize, PROJ_SMEM);
    cudaFuncSetAttribute(attn_pass1, cudaFuncAttributeMaxDynamicSharedMemorySize, P1_SMEM);

    __nv_bfloat16* d_imgh = nullptr; cudaGetSymbolAddress((void**)&d_imgh, g_imgh);
    __nv_bfloat16* d_pch  = nullptr; cudaGetSymbolAddress((void**)&d_pch,  g_pch);
    __nv_bfloat16* d_wqh  = nullptr; cudaGetSymbolAddress((void**)&d_wqh,  g_wqh);
    __nv_bfloat16* d_wkh  = nullptr; cudaGetSymbolAddress((void**)&d_wkh,  g_wkh);

    dim3 blk(256);
    dim3 blk2(512);
    cvt_x_kernel<CK><<<dim3(NN / 32, CK / 32, BB), dim3(32, 8)>>>(pc2d, d_pch);      // 0
    cvt_wqk_kernel<<<256, blk>>>(Wq, Wk);                                            // 1
    cvt_x_kernel<CQ><<<dim3(NN / 32, CQ / 32, BB), dim3(32, 8)>>>(img, d_imgh);      // 2
    proj_kernel<CK, 1><<<dim3(NN / 128, CQ / 128, BB), blk2, PROJ_SMEM>>>(d_wkh, d_pch, bk);  // 3 <- profiled
    proj_kernel<CQ, 0><<<dim3(NN / 128, CQ / 128, BB), blk2, PROJ_SMEM>>>(d_wqh, d_imgh, bq); // 4
    attn_pass1<<<dim3(NN / 128, BB), blk2, P1_SMEM>>>();                             // 5
    attn_pass2<<<dim3(2, 32, BB), blk>>>();                                          // 6
    reduce_w_kernel<<<dim3(BB * NN / 256), blk>>>();                                 // 7
    reduce_xw_kernel<<<dim3(CQ + CK, BB), dim3(128)>>>(img, pc2d);                   // 8
    fuse_kernel<<<dim3(1 + CK / 256, BB), blk>>>(Wvi, bvi, Wvp, bvp, gamma1);        // 9
    head_kernel<<<dim3(BB), blk>>>(W1, b1, W2, b2, out);                             // 10
}

// round 9
// speedup vs baseline: 9.9015x; 1.0764x over previous
#include <cuda_runtime.h>
#include <cuda_bf16.h>
#include <math.h>
#include <stdint.h>

#define BB 16
#define CQ 256
#define CK 2048
#define NN 4096
#define NCLS 40

// ---- scratch (static __device__ arrays; no allocation) ----
__device__ __nv_bfloat16 g_imgh[(size_t)BB * NN * CQ];
__device__ __nv_bfloat16 g_pch[(size_t)BB * NN * CK];
__device__ __nv_bfloat16 g_wqh[CQ * CQ];
__device__ __nv_bfloat16 g_wkh[CQ * CK];
__device__ __nv_bfloat16 g_qh[(size_t)BB * NN * CQ];
__device__ __nv_bfloat16 g_kh[(size_t)BB * NN * CQ];
__device__ __nv_bfloat16 g_Sh[(size_t)BB * NN * NN];   // column-permuted per 64-block
__device__ float g_rowmax[BB * NN];
__device__ float g_rowsum[BB * NN];
__device__ float g_wpart[32 * BB * NN];
__device__ float g_w[BB * NN];
__device__ float g_ximg[BB * CQ];
__device__ float g_imgmean[BB * CQ];
__device__ float g_xpc[BB * CK];
__device__ float g_fused[BB * (CQ + CK)];

// ============================================================
// helpers
// ============================================================
__device__ __forceinline__ uint32_t smem_u32(const void* p) {
    uint32_t a;
    asm("{ .reg .u64 t; cvta.to.shared.u64 t, %1; cvt.u32.u64 %0, t; }" : "=r"(a) : "l"(p));
    return a;
}
__device__ __forceinline__ uint32_t packbf(float x, float y) {
    __nv_bfloat162 h = __floats2bfloat162_rn(x, y);
    return *reinterpret_cast<uint32_t*>(&h);
}
__device__ __forceinline__ void mma_bf16(float* c, const uint32_t* a, uint32_t b0, uint32_t b1)
{
    asm volatile(
        "mma.sync.aligned.m16n8k16.row.col.f32.bf16.bf16.f32 "
        "{%0,%1,%2,%3},{%4,%5,%6,%7},{%8,%9},{%0,%1,%2,%3};"
        : "+f"(c[0]), "+f"(c[1]), "+f"(c[2]), "+f"(c[3])
        : "r"(a[0]), "r"(a[1]), "r"(a[2]), "r"(a[3]), "r"(b0), "r"(b1));
}
__device__ __forceinline__ void ldm_x4(uint32_t* r, uint32_t addr)
{
    asm volatile("ldmatrix.sync.aligned.m8n8.x4.shared.b16 {%0,%1,%2,%3}, [%4];"
        : "=r"(r[0]), "=r"(r[1]), "=r"(r[2]), "=r"(r[3]) : "r"(addr));
}
#define CP_A16(dst, src) \
    asm volatile("cp.async.ca.shared.global [%0], [%1], 16;" :: "r"(dst), "l"(src))
#define CP_COMMIT() asm volatile("cp.async.commit_group;" ::: "memory")
#define CP_WAIT1()  asm volatile("cp.async.wait_group 1;" ::: "memory")
#define CP_WAIT0()  asm volatile("cp.async.wait_group 0;" ::: "memory")

// ============================================================
// Merged convert kernel: pc2d/img transpose-convert + weight convert
// grid (128, 73, 16), block (32, 8)
// ============================================================
__global__ __launch_bounds__(256) void cvt_all_kernel(const float* __restrict__ img,
                                                      const float* __restrict__ pc2d,
                                                      const float* __restrict__ Wq,
                                                      const float* __restrict__ Wk)
{
    __shared__ float t[32][33];
    const int tx = threadIdx.x, ty = threadIdx.y;
    const int y = blockIdx.y;

    if (y < 72) {
        const float* in;
        __nv_bfloat16* out;
        int C, c0;
        if (y < 64) { in = pc2d; out = g_pch;  C = CK; c0 = y * 32; }
        else        { in = img;  out = g_imgh; C = CQ; c0 = (y - 64) * 32; }
        const int b = blockIdx.z, n0 = blockIdx.x * 32;
        const float* ib = in + ((size_t)b * C + c0) * NN + n0;
        #pragma unroll
        for (int i = 0; i < 4; i++) {
            int c = ty + i * 8;
            t[c][tx] = ib[(size_t)c * NN + tx];
        }
        __syncthreads();
        __nv_bfloat16* ob = out + ((size_t)b * NN + n0) * C + c0;
        #pragma unroll
        for (int i = 0; i < 4; i++) {
            int r = ty + i * 8;
            ob[(size_t)r * C + tx] = __float2bfloat16_rn(t[tx][r]);
        }
    } else {
        const int tid = ty * 32 + tx;
        const int total = CQ * CQ + CQ * CK;
        int i = (blockIdx.z * 128 + blockIdx.x) * 256 + tid;
        for (; i < total; i += 128 * 16 * 256) {
            if (i < CQ * CQ) g_wqh[i] = __float2bfloat16_rn(Wq[i]);
            else             g_wkh[i - CQ * CQ] = __float2bfloat16_rn(Wk[i - CQ * CQ]);
        }
    }
}

// ============================================================
// Projection GEMM: block 256m x 128n, 512 thr, 16 warps of 32m x 64n.
// K-staged (128/stage), A/B double-buffered, wait_group 1 pipeline.
// out[b][n][m] = W[m,:]·Xh[b][n,:] + bias[m]   (bf16, [n][c] layout)
// ============================================================
#define PJ_PITCH 68
#define PJ_A (256 * PJ_PITCH)
#define PJ_B (128 * PJ_PITCH)
#define PROJ_SMEM ((2 * PJ_A + 2 * PJ_B) * 4)   // 208896 B

template <int KDIM, int WHICH>
__global__ __launch_bounds__(512) void proj_kernel(const __nv_bfloat16* __restrict__ Wh,
                                                   const __nv_bfloat16* __restrict__ Xh,
                                                   const float* __restrict__ bias)
{
    extern __shared__ uint32_t smu[];
    const int b  = blockIdx.z;
    const int n0 = blockIdx.x * 128;
    const int tid = threadIdx.x;
    const int lane = tid & 31, w = tid >> 5;
    const int wq = w & 7, wh = w >> 3;           // 8 m-strips x 2 n-halves
    const int gid = lane >> 2, tig = lane & 3;
    const int NST = KDIM / 128;
    const __nv_bfloat16* Xb = Xh + (size_t)b * NN * KDIM + (size_t)n0 * KDIM;

    const uint32_t sbase = smem_u32(smu);
    const uint32_t aoff = ((wq * 32 + (lane & 15)) * PJ_PITCH + ((lane & 16) ? 4 : 0)) * 4;
    const uint32_t boff = ((wh * 64 + (lane & 7) + ((lane & 16) >> 1)) * PJ_PITCH + ((lane & 8) ? 4 : 0)) * 4;

    float acc[2][8][4];
    #pragma unroll
    for (int mi = 0; mi < 2; mi++)
        #pragma unroll
        for (int t = 0; t < 8; t++)
            #pragma unroll
            for (int j = 0; j < 4; j++) acc[mi][t][j] = 0.f;

    // prologue: stage 0 and stage 1
    #pragma unroll
    for (int st = 0; st < 2; st++) {
        if (st < NST) {
            #pragma unroll
            for (int l = 0; l < 8; l++) {
                int i = tid + l * 512;
                int r = i >> 4, c = i & 15;
                CP_A16(smem_u32(smu + st * PJ_A + r * PJ_PITCH + c * 4),
                       Wh + (size_t)r * KDIM + st * 128 + c * 8);
            }
            #pragma unroll
            for (int l = 0; l < 4; l++) {
                int i = tid + l * 512;
                int r = i >> 4, c = i & 15;
                CP_A16(smem_u32(smu + 2 * PJ_A + st * PJ_B + r * PJ_PITCH + c * 4),
                       Xb + (size_t)r * KDIM + st * 128 + c * 8);
            }
        }
        CP_COMMIT();
    }

    for (int st = 0; st < NST; st++) {
        CP_WAIT1();
        __syncthreads();

        const uint32_t abase = sbase + (uint32_t)((st & 1) * PJ_A) * 4;
        const uint32_t bbase = sbase + (uint32_t)(2 * PJ_A + (st & 1) * PJ_B) * 4;
        #pragma unroll
        for (int ks = 0; ks < 8; ks++) {
            uint32_t a0[4], a1[4];
            ldm_x4(a0, abase + aoff + ks * 32);
            ldm_x4(a1, abase + aoff + 16 * PJ_PITCH * 4 + ks * 32);
            #pragma unroll
            for (int nt = 0; nt < 4; nt++) {
                uint32_t bf[4];
                ldm_x4(bf, bbase + boff + (uint32_t)(nt * 16 * PJ_PITCH) * 4 + ks * 32);
                mma_bf16(acc[0][nt * 2],     a0, bf[0], bf[1]);
                mma_bf16(acc[0][nt * 2 + 1], a0, bf[2], bf[3]);
                mma_bf16(acc[1][nt * 2],     a1, bf[0], bf[1]);
                mma_bf16(acc[1][nt * 2 + 1], a1, bf[2], bf[3]);
            }
        }
        __syncthreads();

        if (st + 2 < NST) {
            const int s2 = st + 2;
            #pragma unroll
            for (int l = 0; l < 8; l++) {
                int i = tid + l * 512;
                int r = i >> 4, c = i & 15;
                CP_A16(smem_u32(smu + (s2 & 1) * PJ_A + r * PJ_PITCH + c * 4),
                       Wh + (size_t)r * KDIM + s2 * 128 + c * 8);
            }
            #pragma unroll
            for (int l = 0; l < 4; l++) {
                int i = tid + l * 512;
                int r = i >> 4, c = i & 15;
                CP_A16(smem_u32(smu + 2 * PJ_A + (s2 & 1) * PJ_B + r * PJ_PITCH + c * 4),
                       Xb + (size_t)r * KDIM + s2 * 128 + c * 8);
            }
        }
        CP_COMMIT();
    }

    // epilogue: + bias, bf16, scatter-store [n][c]
    __nv_bfloat16* out = (WHICH == 0) ? g_qh : g_kh;
    #pragma unroll
    for (int mi = 0; mi < 2; mi++) {
        const int R0 = wq * 32 + mi * 16 + gid;
        const float bv0 = bias[R0], bv1 = bias[R0 + 8];
        #pragma unroll
        for (int t = 0; t < 8; t++) {
            int n = n0 + wh * 64 + t * 8 + tig * 2;
            __nv_bfloat16* p0 = out + ((size_t)b * NN + n) * CQ;
            __nv_bfloat16* p1 = p0 + CQ;
            p0[R0]     = __float2bfloat16_rn(acc[mi][t][0] + bv0);
            p1[R0]     = __float2bfloat16_rn(acc[mi][t][1] + bv0);
            p0[R0 + 8] = __float2bfloat16_rn(acc[mi][t][2] + bv1);
            p1[R0 + 8] = __float2bfloat16_rn(acc[mi][t][3] + bv1);
        }
    }
}

// ============================================================
// Attention pass 1: block = 256 m-rows (q resident), sweep n in 128-steps.
// 512 thr, 16 warps of 32m x 64n. B staged per (s, kc) 128n x 128k,
// 2 buffers, wait_group 1. S stored bf16 column-permuted; online row stats.
// ============================================================
#define P1_PITCH 132
#define P1_A (256 * P1_PITCH)                   // 33792 u32
#define P1_B (128 * PJ_PITCH)                   // 8704 u32 (pitch 68)
#define P1_SMEM ((P1_A + 2 * P1_B + 1024) * 4)  // 208896 B

__global__ __launch_bounds__(512) void attn_pass1()
{
    extern __shared__ uint32_t smu[];
    float* smM = reinterpret_cast<float*>(smu + P1_A + 2 * P1_B);   // [2][256]
    float* smS = smM + 512;

    const int b  = blockIdx.y;
    const int m0 = blockIdx.x * 256;
    const int tid = threadIdx.x;
    const int lane = tid & 31, w = tid >> 5;
    const int wq = w & 7, wh = w >> 3;
    const int gid = lane >> 2, tig = lane & 3;

    const uint32_t sbase = smem_u32(smu);
    const uint32_t aoff = ((wq * 32 + (lane & 15)) * P1_PITCH + ((lane & 16) ? 4 : 0)) * 4;
    const uint32_t boff = ((wh * 64 + (lane & 7) + ((lane & 16) >> 1)) * PJ_PITCH + ((lane & 8) ? 4 : 0)) * 4;

    // stage loader: stage = (s<<1)|kc
    auto load_stage = [&](int st) {
        const int s = st >> 1, kc = st & 1;
        const __nv_bfloat16* src = g_kh + ((size_t)b * NN + s * 128) * CQ + kc * 128;
        #pragma unroll
        for (int l = 0; l < 4; l++) {
            int i = tid + l * 512;
            int r = i >> 4, c = i & 15;
            CP_A16(smem_u32(smu + P1_A + (st & 1) * P1_B + r * PJ_PITCH + c * 4),
                   src + (size_t)r * CQ + c * 8);
        }
    };

    // prologue: resident A (q-tile 256 x 256) + stages 0,1
    {
        #pragma unroll
        for (int l = 0; l < 16; l++) {
            int i = tid + l * 512;
            int r = i >> 5, c = i & 31;
            CP_A16(smem_u32(smu + r * P1_PITCH + c * 4),
                   g_qh + ((size_t)b * NN + m0 + r) * CQ + c * 8);
        }
        load_stage(0);
        CP_COMMIT();
        load_stage(1);
        CP_COMMIT();
    }

    float acc[2][8][4];
    #pragma unroll
    for (int mi = 0; mi < 2; mi++)
        #pragma unroll
        for (int t = 0; t < 8; t++)
            #pragma unroll
            for (int j = 0; j < 4; j++) acc[mi][t][j] = 0.f;

    float run_m[4], run_s[4];
    #pragma unroll
    for (int k = 0; k < 4; k++) { run_m[k] = -INFINITY; run_s[k] = 0.f; }

    for (int st = 0; st < 64; st++) {
        CP_WAIT1();
        __syncthreads();

        const int kc = st & 1;
        const uint32_t bbase = sbase + (uint32_t)(P1_A + (st & 1) * P1_B) * 4;
        #pragma unroll
        for (int ks = 0; ks < 8; ks++) {
            uint32_t a0[4], a1[4];
            ldm_x4(a0, sbase + aoff + (kc * 8 + ks) * 32);
            ldm_x4(a1, sbase + aoff + 16 * P1_PITCH * 4 + (kc * 8 + ks) * 32);
            #pragma unroll
            for (int nt = 0; nt < 4; nt++) {
                uint32_t bf[4];
                ldm_x4(bf, bbase + boff + (uint32_t)(nt * 16 * PJ_PITCH) * 4 + ks * 32);
                mma_bf16(acc[0][nt * 2],     a0, bf[0], bf[1]);
                mma_bf16(acc[0][nt * 2 + 1], a0, bf[2], bf[3]);
                mma_bf16(acc[1][nt * 2],     a1, bf[0], bf[1]);
                mma_bf16(acc[1][nt * 2 + 1], a1, bf[2], bf[3]);
            }
        }
        __syncthreads();

        if (st + 2 < 64) load_stage(st + 2);
        CP_COMMIT();

        if (st & 1) {
            const int s = st >> 1;
            #pragma unroll
            for (int mi = 0; mi < 2; mi++) {
                #pragma unroll
                for (int rr = 0; rr < 2; rr++) {
                    const int k = mi * 2 + rr;
                    float vm = -INFINITY;
                    #pragma unroll
                    for (int t = 0; t < 8; t++)
                        vm = fmaxf(vm, fmaxf(acc[mi][t][rr * 2], acc[mi][t][rr * 2 + 1]));
                    vm = fmaxf(vm, __shfl_xor_sync(0xffffffffu, vm, 1));
                    vm = fmaxf(vm, __shfl_xor_sync(0xffffffffu, vm, 2));
                    const float nm = fmaxf(run_m[k], vm);
                    float ss = 0.f;
                    #pragma unroll
                    for (int t = 0; t < 8; t++)
                        ss += __expf(acc[mi][t][rr * 2] - nm) + __expf(acc[mi][t][rr * 2 + 1] - nm);
                    ss += __shfl_xor_sync(0xffffffffu, ss, 1);
                    ss += __shfl_xor_sync(0xffffffffu, ss, 2);
                    run_s[k] = run_s[k] * __expf(run_m[k] - nm) + ss;
                    run_m[k] = nm;

                    // coalesced permuted S store: 32B per row per lane
                    const int row = m0 + wq * 32 + mi * 16 + gid + rr * 8;
                    uint32_t pk[8];
                    #pragma unroll
                    for (int t = 0; t < 8; t++)
                        pk[t] = packbf(acc[mi][t][rr * 2], acc[mi][t][rr * 2 + 1]);
                    __nv_bfloat16* dst = g_Sh + ((size_t)b * NN + row) * NN + s * 128 + wh * 64 + tig * 16;
                    *reinterpret_cast<uint4*>(dst)     = *reinterpret_cast<uint4*>(pk);
                    *reinterpret_cast<uint4*>(dst + 8) = *reinterpret_cast<uint4*>(pk + 4);
                }
            }
            #pragma unroll
            for (int mi = 0; mi < 2; mi++)
                #pragma unroll
                for (int t = 0; t < 8; t++)
                    #pragma unroll
                    for (int j = 0; j < 4; j++) acc[mi][t][j] = 0.f;
        }
    }

    // merge the two n-halves' stats
    if (tig == 0) {
        #pragma unroll
        for (int k = 0; k < 4; k++) {
            const int r = wq * 32 + (k >> 1) * 16 + gid + (k & 1) * 8;
            smM[wh * 256 + r] = run_m[k];
            smS[wh * 256 + r] = run_s[k];
        }
    }
    __syncthreads();
    if (tid < 256) {
        float ma = smM[tid], mb = smM[256 + tid];
        float sa = smS[tid], sb = smS[256 + tid];
        float nm = fmaxf(ma, mb);
        g_rowmax[b * NN + m0 + tid] = nm;
        g_rowsum[b * NN + m0 + tid] = sa * __expf(ma - nm) + sb * __expf(mb - nm);
    }
}

// ============================================================
// Attention pass 2: stream bf16 S (permuted order), per-slice column sums.
// ============================================================
__global__ __launch_bounds__(256) void attn_pass2()
{
    __shared__ float rm[128], rz[128];
    const int b  = blockIdx.z;
    const int ms = blockIdx.y;
    const int nb = blockIdx.x * 2048;
    const int tid = threadIdx.x;

    if (tid < 128) {
        rm[tid] = g_rowmax[b * NN + ms * 128 + tid];
        rz[tid] = 1.0f / g_rowsum[b * NN + ms * 128 + tid];
    }
    __syncthreads();

    const __nv_bfloat16* Sp = g_Sh + ((size_t)b * NN + ms * 128) * NN + nb + tid * 8;
    float a[8];
    #pragma unroll
    for (int i = 0; i < 8; i++) a[i] = 0.f;

    for (int m = 0; m < 128; m++) {
        uint4 r = *reinterpret_cast<const uint4*>(Sp + (size_t)m * NN);
        float mx = rm[m], z = rz[m];
        __nv_bfloat162 p0 = *reinterpret_cast<__nv_bfloat162*>(&r.x);
        __nv_bfloat162 p1 = *reinterpret_cast<__nv_bfloat162*>(&r.y);
        __nv_bfloat162 p2 = *reinterpret_cast<__nv_bfloat162*>(&r.z);
        __nv_bfloat162 p3 = *reinterpret_cast<__nv_bfloat162*>(&r.w);
        a[0] += __expf(__bfloat162float(p0.x) - mx) * z;
        a[1] += __expf(__bfloat162float(p0.y) - mx) * z;
        a[2] += __expf(__bfloat162float(p1.x) - mx) * z;
        a[3] += __expf(__bfloat162float(p1.y) - mx) * z;
        a[4] += __expf(__bfloat162float(p2.x) - mx) * z;
        a[5] += __expf(__bfloat162float(p2.y) - mx) * z;
        a[6] += __expf(__bfloat162float(p3.x) - mx) * z;
        a[7] += __expf(__bfloat162float(p3.y) - mx) * z;
    }
    const float sc = 1.0f / NN;
    float* wp = g_wpart + (size_t)ms * (BB * NN) + b * NN + nb + tid * 8;
    *reinterpret_cast<float4*>(wp)     = make_float4(a[0] * sc, a[1] * sc, a[2] * sc, a[3] * sc);
    *reinterpret_cast<float4*>(wp + 4) = make_float4(a[4] * sc, a[5] * sc, a[6] * sc, a[7] * sc);
}

// reduce + inverse column permutation: stored = ((a&7)>>1)*16 + ((a>>3)&7)*2 + (a&1)
__global__ void reduce_w_kernel()
{
    const int flat = blockIdx.x * 256 + threadIdx.x;
    const int a = flat & 63;
    const int sa = ((a & 7) >> 1) * 16 + ((a >> 3) & 7) * 2 + (a & 1);
    const int src = (flat & ~63) | sa;
    float s = 0.f;
    #pragma unroll
    for (int ms = 0; ms < 32; ms++) s += g_wpart[ms * (BB * NN) + src];
    g_w[flat] = s;
}

// ============================================================
// Weighted/plain reductions over spatial axis
// ============================================================
__global__ void reduce_xw_kernel(const float* __restrict__ img,
                                 const float* __restrict__ pc2d)
{
    const int b = blockIdx.y;
    const int c = blockIdx.x;
    const int t = threadIdx.x;
    const float* wv = g_w + b * NN;
    __shared__ float s1s[4], s2s[4];

    float s1 = 0.f, s2 = 0.f;
    if (c < CQ) {
        const float* row = img + ((size_t)b * CQ + c) * NN;
        for (int n = t; n < NN; n += 128) { float x = row[n]; s1 += x * wv[n]; s2 += x; }
    } else {
        const float* row = pc2d + ((size_t)b * CK + (c - CQ)) * NN;
        for (int n = t; n < NN; n += 128) s1 += row[n] * wv[n];
    }
    #pragma unroll
    for (int o = 16; o; o >>= 1) {
        s1 += __shfl_xor_sync(0xffffffffu, s1, o);
        s2 += __shfl_xor_sync(0xffffffffu, s2, o);
    }
    if ((t & 31) == 0) { s1s[t >> 5] = s1; s2s[t >> 5] = s2; }
    __syncthreads();
    if (t == 0) {
        float a = s1s[0] + s1s[1] + s1s[2] + s1s[3];
        float m = s2s[0] + s2s[1] + s2s[2] + s2s[3];
        if (c < CQ) {
            g_ximg[b * CQ + c] = a;
            g_imgmean[b * CQ + c] = m * (1.0f / NN);
        } else {
            g_xpc[b * CK + (c - CQ)] = a;
        }
    }
}

// ============================================================
// Fused vector
// ============================================================
__global__ void fuse_kernel(const float* __restrict__ Wvi, const float* __restrict__ bvi,
                            const float* __restrict__ Wvp, const float* __restrict__ bvp,
                            const float* __restrict__ gamma1)
{
    const int b = blockIdx.y;
    const int chunk = blockIdx.x;
    const int t = threadIdx.x;
    __shared__ float xs[2048];

    if (chunk == 0) {
        if (t < CQ) xs[t] = g_ximg[b * CQ + t];
        __syncthreads();
        float acc = 0.f;
        const float* wr = Wvi + (size_t)t * CQ;
        for (int i = 0; i < CQ; i++) acc += wr[i] * xs[i];
        float g = gamma1[0];
        g_fused[b * (CQ + CK) + t] = g * (acc + bvi[t]) + g_imgmean[b * CQ + t];
    } else {
        for (int i = t; i < CK; i += 256) xs[i] = g_xpc[b * CK + i];
        __syncthreads();
        int c2 = (chunk - 1) * 256 + t;
        float acc = 0.f;
        const float* wr = Wvp + (size_t)c2 * CK;
        for (int i = 0; i < CK; i++) acc += wr[i] * xs[i];
        g_fused[b * (CQ + CK) + CQ + c2] = acc + bvp[c2];
    }
}

// ============================================================
// MLP head + log_softmax
// ============================================================
__device__ __forceinline__ float warp_red(float v)
{
    #pragma unroll
    for (int o = 16; o; o >>= 1) v += __shfl_xor_sync(0xffffffffu, v, o);
    return v;
}

__global__ void head_kernel(const float* __restrict__ W1, const float* __restrict__ b1,
                            const float* __restrict__ W2, const float* __restrict__ b2,
                            float* __restrict__ out)
{
    const int b = blockIdx.x;
    __shared__ float fs[CQ + CK];
    __shared__ float hs[1024];
    __shared__ float lg[NCLS];
    __shared__ float mxs, lses;
    const int tid = threadIdx.x;
    const int warp = tid >> 5, lane = tid & 31;

    for (int i = tid; i < CQ + CK; i += 256) fs[i] = g_fused[b * (CQ + CK) + i];
    __syncthreads();

    for (int j = warp; j < 1024; j += 8) {
        const float* wr = W1 + (size_t)j * (CQ + CK);
        float s = 0.f;
        for (int i = lane; i < CQ + CK; i += 32) s += fs[i] * wr[i];
        s = warp_red(s);
        if (lane == 0) hs[j] = fmaxf(s + b1[j], 0.f);
    }
    __syncthreads();

    for (int k = warp; k < NCLS; k += 8) {
        const float* wr = W2 + (size_t)k * 1024;
        float s = 0.f;
        for (int i = lane; i < 1024; i += 32) s += hs[i] * wr[i];
        s = warp_red(s);
        if (lane == 0) lg[k] = s + b2[k];
    }
    __syncthreads();

    if (tid == 0) {
        float m = -INFINITY;
        for (int k = 0; k < NCLS; k++) m = fmaxf(m, lg[k]);
        float s = 0.f;
        for (int k = 0; k < NCLS; k++) s += expf(lg[k] - m);
        mxs = m; lses = logf(s);
    }
    __syncthreads();
    if (tid < NCLS) out[b * NCLS + tid] = lg[tid] - mxs - lses;
}

// ============================================================
extern "C" void kernel_launch(void* const* d_in, const int* in_sizes, int n_in,
                              void* d_out, int out_size)
{
    const float* img    = (const float*)d_in[0];
    const float* pc2d   = (const float*)d_in[1];
    const float* Wq     = (const float*)d_in[2];
    const float* bq     = (const float*)d_in[3];
    const float* Wk     = (const float*)d_in[4];
    const float* bk     = (const float*)d_in[5];
    const float* Wvi    = (const float*)d_in[6];
    const float* bvi    = (const float*)d_in[7];
    const float* Wvp    = (const float*)d_in[8];
    const float* bvp    = (const float*)d_in[9];
    const float* gamma1 = (const float*)d_in[10];
    const float* W1     = (const float*)d_in[11];
    const float* b1     = (const float*)d_in[12];
    const float* W2     = (const float*)d_in[13];
    const float* b2     = (const float*)d_in[14];
    float* out = (float*)d_out;

    cudaFuncSetAttribute(proj_kernel<CQ, 0>, cudaFuncAttributeMaxDynamicSharedMemorySize, PROJ_SMEM);
    cudaFuncSetAttribute(proj_kernel<CK, 1>, cudaFuncAttributeMaxDynamicSharedMemorySize, PROJ_SMEM);
    cudaFuncSetAttribute(attn_pass1, cudaFuncAttributeMaxDynamicSharedMemorySize, P1_SMEM);

    __nv_bfloat16* d_imgh = nullptr; cudaGetSymbolAddress((void**)&d_imgh, g_imgh);
    __nv_bfloat16* d_pch  = nullptr; cudaGetSymbolAddress((void**)&d_pch,  g_pch);
    __nv_bfloat16* d_wqh  = nullptr; cudaGetSymbolAddress((void**)&d_wqh,  g_wqh);
    __nv_bfloat16* d_wkh  = nullptr; cudaGetSymbolAddress((void**)&d_wkh,  g_wkh);

    dim3 blk(256);
    dim3 blk2(512);
    cvt_all_kernel<<<dim3(128, 73, BB), dim3(32, 8)>>>(img, pc2d, Wq, Wk);                    // 0
    proj_kernel<CK, 1><<<dim3(NN / 128, 1, BB), blk2, PROJ_SMEM>>>(d_wkh, d_pch, bk);         // 1
    proj_kernel<CQ, 0><<<dim3(NN / 128, 1, BB), blk2, PROJ_SMEM>>>(d_wqh, d_imgh, bq);        // 2
    attn_pass1<<<dim3(NN / 256, BB), blk2, P1_SMEM>>>();                                      // 3 <- profiled
    attn_pass2<<<dim3(2, 32, BB), blk>>>();                                                   // 4
    reduce_w_kernel<<<dim3(BB * NN / 256), blk>>>();                                          // 5
    reduce_xw_kernel<<<dim3(CQ + CK, BB), dim3(128)>>>(img, pc2d);                            // 6
    fuse_kernel<<<dim3(1 + CK / 256, BB), blk>>>(Wvi, bvi, Wvp, bvp, gamma1);                 // 7
    head_kernel<<<dim3(BB), blk>>>(W1, b1, W2, b2, out);                                      // 8
}